// round 4
// baseline (speedup 1.0000x reference)
#include <cuda_runtime.h>
#include <stdint.h>

#define NNODES 100000
#define NEDGES 1600000
#define NFEAT  128
#define NHID   64
#define NCLASS 40

// ---------------- scratch (static device globals; no allocation) ----------------
__device__ int   g_is64;
__device__ int   g_src[NEDGES];
__device__ int   g_dst[NEDGES];
__device__ int   g_cnt[NNODES];
__device__ int   g_cursor[NNODES];
__device__ int   g_rowstart[NNODES];
__device__ int   g_bsum[256];
__device__ int   g_boff[256];
__device__ int   g_csr[NEDGES];
__device__ float g_dis[NNODES];
__device__ float g_xw[(size_t)NNODES * NHID];    // dis[n] * (x @ W1)
__device__ float g_h [(size_t)NNODES * NHID];    // relu(agg1 + b1)
__device__ float g_hw[(size_t)NNODES * NCLASS];  // dis[n] * (h @ W2)

// ---------------- threefry2x32, key = (0, 42)  (jax.random.key(42)) -------------
__device__ __forceinline__ void threefry_0_42(uint32_t x0, uint32_t x1,
                                              uint32_t& o0, uint32_t& o1) {
    const uint32_t k0 = 0u, k1 = 42u;
    const uint32_t k2 = k0 ^ k1 ^ 0x1BD11BDAu;
    x0 += k0; x1 += k1;
#define TF_RND(R) { x0 += x1; x1 = (x1 << (R)) | (x1 >> (32 - (R))); x1 ^= x0; }
    TF_RND(13) TF_RND(15) TF_RND(26) TF_RND(6)   x0 += k1; x1 += k2 + 1u;
    TF_RND(17) TF_RND(29) TF_RND(16) TF_RND(24)  x0 += k2; x1 += k0 + 2u;
    TF_RND(13) TF_RND(15) TF_RND(26) TF_RND(6)   x0 += k0; x1 += k1 + 3u;
    TF_RND(17) TF_RND(29) TF_RND(16) TF_RND(24)  x0 += k1; x1 += k2 + 4u;
    TF_RND(13) TF_RND(15) TF_RND(26) TF_RND(6)   x0 += k2; x1 += k0 + 5u;
#undef TF_RND
    o0 = x0; o1 = x1;
}

// JAX threefry_partitionable random_bits, bit_width=32 (modern JAX default):
//   counts1, counts2 = iota_2x32_shape(shape)        (hi, lo of flat index)
//   bits1, bits2 = threefry2x32(key, counts1, counts2)
//   bits = convert_element_type(bits1 ^ bits2, uint32)    <-- XOR fold
// uniform u = (bits>>9)/2^23, keep = u < 0.5  <=>  MSB(bits)==0.
__device__ __forceinline__ bool dropout_keep(uint32_t e) {
    uint32_t o0, o1;
    threefry_0_42(0u, e, o0, o1);
    return ((o0 ^ o1) & 0x80000000u) == 0u;
}

// ---------------- dtype detection + edge decode ----------------
__global__ void k_detect(const void* __restrict__ ei) {
    __shared__ unsigned ok;
    if (threadIdx.x == 0) ok = 1u;
    __syncthreads();
    const unsigned long long* p = (const unsigned long long*)ei;
    unsigned long long v = p[threadIdx.x];   // first 512B: in-bounds for both layouts
    if (v >> 32) atomicAnd(&ok, 0u);
    __syncthreads();
    if (threadIdx.x == 0) g_is64 = (int)ok;
}

__global__ void k_decode(const void* __restrict__ ei, int E) {
    int e = blockIdx.x * blockDim.x + threadIdx.x;
    if (e >= E) return;
    int s, d;
    if (g_is64) {
        const long long* p = (const long long*)ei;
        s = (int)p[e];
        d = (int)p[(size_t)E + e];
    } else {
        const int* p = (const int*)ei;
        s = p[e];
        d = p[(size_t)E + e];
    }
    g_src[e] = s;
    g_dst[e] = d;
}

// ---------------- CSR build ----------------
__global__ void k_init(int N) {
    int i = blockIdx.x * blockDim.x + threadIdx.x;
    if (i < N) { g_cnt[i] = 0; g_cursor[i] = 0; }
}

__global__ void k_hist(int E, int N) {
    int e = blockIdx.x * blockDim.x + threadIdx.x;
    if (e < E) {
        int d = g_dst[e];
        if ((unsigned)d < (unsigned)N) atomicAdd(&g_cnt[d], 1);
    }
}

__global__ void k_dis(int N) {
    int i = blockIdx.x * blockDim.x + threadIdx.x;
    if (i < N) g_dis[i] = rsqrtf((float)g_cnt[i] + 1.0f);  // deg includes self-loop
}

__global__ void k_scan1(int N) {
    __shared__ int sm[1024];
    int i = blockIdx.x * 1024 + threadIdx.x;
    int v = (i < N) ? g_cnt[i] : 0;
    sm[threadIdx.x] = v;
    __syncthreads();
    for (int off = 1; off < 1024; off <<= 1) {
        int t = (threadIdx.x >= off) ? sm[threadIdx.x - off] : 0;
        __syncthreads();
        sm[threadIdx.x] += t;
        __syncthreads();
    }
    if (i < N) g_rowstart[i] = sm[threadIdx.x] - v;  // exclusive within block
    if (threadIdx.x == 1023) g_bsum[blockIdx.x] = sm[1023];
}

__global__ void k_scan2(int nb) {
    if (threadIdx.x == 0) {
        int run = 0;
        for (int b = 0; b < nb; b++) { g_boff[b] = run; run += g_bsum[b]; }
    }
}

__global__ void k_scan3(int N) {
    int i = blockIdx.x * blockDim.x + threadIdx.x;
    if (i < N) g_rowstart[i] += g_boff[i >> 10];
}

__global__ void k_fill(int E, int N) {
    int e = blockIdx.x * blockDim.x + threadIdx.x;
    if (e < E) {
        int s = g_src[e];
        int d = g_dst[e];
        if ((unsigned)d < (unsigned)N && (unsigned)s < (unsigned)N) {
            int p = atomicAdd(&g_cursor[d], 1);
            g_csr[g_rowstart[d] + p] = s;
        }
    }
}

// ---------------- layer 1 GEMM fused with dropout + dis prescale ----------------
// Warp per node; each lane computes its own 4 per-element threefry masks.
__global__ void k_gemm1(const float* __restrict__ X, const float* __restrict__ W1, int N) {
    __shared__ float Wp[NFEAT][NHID];   // paired: Wp[k][2l] = W[k][l], Wp[k][2l+1] = W[k][l+32]
    __shared__ float xs[8][NFEAT];      // per-warp dropout'd inputs

    int tid = threadIdx.x, w = tid >> 5, l = tid & 31;
    for (int idx = tid; idx < NFEAT * NHID; idx += blockDim.x) {
        int k = idx >> 6, j = idx & 63;
        Wp[k][((j & 31) << 1) | (j >> 5)] = W1[idx];
    }
    __syncthreads();

    int n = blockIdx.x * 8 + w;
    if (n >= N) return;

#pragma unroll
    for (int t = 0; t < 4; t++) {
        int f = l + 32 * t;
        uint32_t e = (uint32_t)n * 128u + (uint32_t)f;
        float xv = X[(size_t)n * NFEAT + f] * 2.0f;
        xs[w][f] = dropout_keep(e) ? xv : 0.0f;
    }
    __syncwarp();

    float y0 = 0.f, y1 = 0.f;
#pragma unroll 8
    for (int k = 0; k < NFEAT; k++) {
        float x = xs[w][k];
        float2 wv = *(const float2*)&Wp[k][l << 1];
        y0 = fmaf(x, wv.x, y0);
        y1 = fmaf(x, wv.y, y1);
    }
    float dn = g_dis[n];
    g_xw[(size_t)n * NHID + l]      = y0 * dn;
    g_xw[(size_t)n * NHID + 32 + l] = y1 * dn;
}

// ---------------- layer 1 aggregation (gather, warp per node) -------------------
__global__ void k_gather1(const float* __restrict__ b1, int N) {
    int n = (blockIdx.x * blockDim.x + threadIdx.x) >> 5;
    int l = threadIdx.x & 31;
    if (n >= N) return;

    float2 acc = *(const float2*)&g_xw[(size_t)n * NHID + 2 * l];  // self-loop term
    int beg = g_rowstart[n], cnt = g_cursor[n];
    const int* cs = g_csr + beg;
    for (int i = 0; i < cnt; i++) {
        int s = cs[i];
        float2 v = *(const float2*)&g_xw[(size_t)s * NHID + 2 * l];
        acc.x += v.x; acc.y += v.y;
    }
    float dn = g_dis[n];
    float2 bb = *(const float2*)&b1[2 * l];
    float2 o;
    o.x = fmaxf(fmaf(acc.x, dn, bb.x), 0.0f);
    o.y = fmaxf(fmaf(acc.y, dn, bb.y), 0.0f);
    *(float2*)&g_h[(size_t)n * NHID + 2 * l] = o;
}

// ---------------- layer 2 GEMM (warp per node, shfl-broadcast) ------------------
__global__ void k_gemm2(const float* __restrict__ W2, int N) {
    __shared__ float W2s[NHID][64];  // 40 cols used; padded to avoid OOB garbage math
    int tid = threadIdx.x, l = tid & 31;
    for (int idx = tid; idx < NHID * 64; idx += blockDim.x)
        ((float*)W2s)[idx] = 0.0f;
    __syncthreads();
    for (int idx = tid; idx < NHID * NCLASS; idx += blockDim.x)
        W2s[idx / NCLASS][idx % NCLASS] = W2[idx];
    __syncthreads();

    int n = (blockIdx.x * blockDim.x + tid) >> 5;
    if (n >= N) return;

    float h0 = g_h[(size_t)n * NHID + l];
    float h1 = g_h[(size_t)n * NHID + 32 + l];
    float y0 = 0.f, y1 = 0.f;
#pragma unroll
    for (int k = 0; k < 32; k++) {
        float hk = __shfl_sync(0xffffffffu, h0, k);
        y0 = fmaf(hk, W2s[k][l], y0);
        y1 = fmaf(hk, W2s[k][32 + l], y1);
    }
#pragma unroll
    for (int k = 0; k < 32; k++) {
        float hk = __shfl_sync(0xffffffffu, h1, k);
        y0 = fmaf(hk, W2s[32 + k][l], y0);
        y1 = fmaf(hk, W2s[32 + k][32 + l], y1);
    }
    float dn = g_dis[n];
    g_hw[(size_t)n * NCLASS + l] = y0 * dn;
    if (l < 8) g_hw[(size_t)n * NCLASS + 32 + l] = y1 * dn;
}

// ---------------- layer 2 aggregation + bias -> output --------------------------
__global__ void k_gather2(const float* __restrict__ b2, float* __restrict__ out, int N) {
    int n = (blockIdx.x * blockDim.x + threadIdx.x) >> 5;
    int l = threadIdx.x & 31;
    if (n >= N) return;

    float a0 = g_hw[(size_t)n * NCLASS + l];                       // self-loop
    float a1 = (l < 8) ? g_hw[(size_t)n * NCLASS + 32 + l] : 0.0f;
    int beg = g_rowstart[n], cnt = g_cursor[n];
    const int* cs = g_csr + beg;
    for (int i = 0; i < cnt; i++) {
        int s = cs[i];
        a0 += g_hw[(size_t)s * NCLASS + l];
        if (l < 8) a1 += g_hw[(size_t)s * NCLASS + 32 + l];
    }
    float dn = g_dis[n];
    out[(size_t)n * NCLASS + l] = fmaf(a0, dn, b2[l]);
    if (l < 8) out[(size_t)n * NCLASS + 32 + l] = fmaf(a1, dn, b2[32 + l]);
}

// ---------------- launch ----------------
extern "C" void kernel_launch(void* const* d_in, const int* in_sizes, int n_in,
                              void* d_out, int out_size) {
    const float* X  = (const float*)d_in[0];
    const void*  ei = (const void*)d_in[1];
    const float* W1 = (const float*)d_in[2];
    const float* b1 = (const float*)d_in[3];
    const float* W2 = (const float*)d_in[4];
    const float* b2 = (const float*)d_in[5];
    float*       out = (float*)d_out;

    int N = in_sizes[0] / NFEAT;   // 100000
    int E = in_sizes[1] / 2;       // 1600000 (element count is dtype-independent)
    int nb = (N + 1023) / 1024;

    k_detect<<<1, 64>>>(ei);
    k_decode<<<(E + 255) / 256, 256>>>(ei, E);
    k_init  <<<(N + 255) / 256, 256>>>(N);
    k_hist  <<<(E + 255) / 256, 256>>>(E, N);
    k_dis   <<<(N + 255) / 256, 256>>>(N);
    k_scan1 <<<nb, 1024>>>(N);
    k_scan2 <<<1, 32>>>(nb);
    k_scan3 <<<(N + 1023) / 1024, 1024>>>(N);
    k_fill  <<<(E + 255) / 256, 256>>>(E, N);

    k_gemm1  <<<(N + 7) / 8, 256>>>(X, W1, N);
    k_gather1<<<(N + 7) / 8, 256>>>(b1, N);
    k_gemm2  <<<(N + 7) / 8, 256>>>(W2, N);
    k_gather2<<<(N + 7) / 8, 256>>>(b2, out, N);
}

// round 5
// speedup vs baseline: 1.8890x; 1.8890x over previous
#include <cuda_runtime.h>
#include <stdint.h>

#define NNODES 100000
#define NEDGES 1600000
#define NFEAT  128
#define NHID   64
#define NCLASS 40
#define HWS    64   // padded row stride for g_hw (256B-aligned rows)

// ---------------- scratch (static device globals; no allocation) ----------------
__device__ int   g_src[NEDGES];
__device__ int   g_dst[NEDGES];
__device__ int   g_cnt[NNODES];
__device__ int   g_cursor[NNODES];
__device__ int   g_rowstart[NNODES];
__device__ int   g_bsum[128];
__device__ int   g_csr[NEDGES];
__device__ float g_dis[NNODES];
// permuted layout: g_xw[n*64 + 2l] = col l, [n*64 + 2l+1] = col l+32, pre-scaled by dis[n]
__device__ float g_xw[(size_t)NNODES * NHID];
__device__ float g_hw[(size_t)NNODES * HWS];   // dis[n] * (h @ W2), cols 0..39

// ---------------- threefry2x32, key = (0, 42) ----------------
__device__ __forceinline__ void threefry_0_42(uint32_t x0, uint32_t x1,
                                              uint32_t& o0, uint32_t& o1) {
    const uint32_t k0 = 0u, k1 = 42u;
    const uint32_t k2 = k0 ^ k1 ^ 0x1BD11BDAu;
    x0 += k0; x1 += k1;
#define TF_RND(R) { x0 += x1; x1 = (x1 << (R)) | (x1 >> (32 - (R))); x1 ^= x0; }
    TF_RND(13) TF_RND(15) TF_RND(26) TF_RND(6)   x0 += k1; x1 += k2 + 1u;
    TF_RND(17) TF_RND(29) TF_RND(16) TF_RND(24)  x0 += k2; x1 += k0 + 2u;
    TF_RND(13) TF_RND(15) TF_RND(26) TF_RND(6)   x0 += k0; x1 += k1 + 3u;
    TF_RND(17) TF_RND(29) TF_RND(16) TF_RND(24)  x0 += k1; x1 += k2 + 4u;
    TF_RND(13) TF_RND(15) TF_RND(26) TF_RND(6)   x0 += k2; x1 += k0 + 5u;
#undef TF_RND
    o0 = x0; o1 = x1;
}

// JAX threefry_partitionable bits32: bits = out0 ^ out1 of threefry(key,(hi,lo)); keep = MSB==0
__device__ __forceinline__ bool dropout_keep(uint32_t e) {
    uint32_t o0, o1;
    threefry_0_42(0u, e, o0, o1);
    return ((o0 ^ o1) & 0x80000000u) == 0u;
}

// ---------------- init ----------------
__global__ void k_init(int N) {
    int i = blockIdx.x * blockDim.x + threadIdx.x;
    if (i < N) { g_cnt[i] = 0; g_cursor[i] = 0; }
}

// ---------------- decode (dtype-agnostic) + histogram, fused ----------------
__global__ void k_prep(const void* __restrict__ ei, int E, int N) {
    __shared__ int s_is64;
    if (threadIdx.x < 32) {
        const unsigned long long* p = (const unsigned long long*)ei;
        unsigned long long v0 = p[threadIdx.x];
        unsigned long long v1 = p[32 + threadIdx.x];
        unsigned any = __ballot_sync(0xffffffffu, ((v0 >> 32) | (v1 >> 32)) != 0ull);
        if (threadIdx.x == 0) s_is64 = (any == 0u);   // int64 values < 2^32 -> hi words all zero
    }
    __syncthreads();
    int is64 = s_is64;
    int e = blockIdx.x * blockDim.x + threadIdx.x;
    if (e >= E) return;
    int s, d;
    if (is64) {
        const long long* p = (const long long*)ei;
        s = (int)p[e];
        d = (int)p[(size_t)E + e];
    } else {
        const int* p = (const int*)ei;
        s = p[e];
        d = p[(size_t)E + e];
    }
    g_src[e] = s;
    g_dst[e] = d;
    if ((unsigned)d < (unsigned)N) atomicAdd(&g_cnt[d], 1);
}

// ---------------- scan (block-local) + dis, fused ----------------
__global__ void k_scan1(int N) {
    __shared__ int sm[1024];
    int i = blockIdx.x * 1024 + threadIdx.x;
    int v = (i < N) ? g_cnt[i] : 0;
    if (i < N) g_dis[i] = rsqrtf((float)v + 1.0f);   // deg includes self-loop
    sm[threadIdx.x] = v;
    __syncthreads();
    for (int off = 1; off < 1024; off <<= 1) {
        int t = (threadIdx.x >= off) ? sm[threadIdx.x - off] : 0;
        __syncthreads();
        sm[threadIdx.x] += t;
        __syncthreads();
    }
    if (i < N) g_rowstart[i] = sm[threadIdx.x] - v;
    if (threadIdx.x == 1023) g_bsum[blockIdx.x] = sm[1023];
}

__global__ void k_scan2(int nb) {
    __shared__ int sm[128];
    int v = (threadIdx.x < nb) ? g_bsum[threadIdx.x] : 0;
    sm[threadIdx.x] = v;
    __syncthreads();
    for (int off = 1; off < 128; off <<= 1) {
        int t = (threadIdx.x >= off) ? sm[threadIdx.x - off] : 0;
        __syncthreads();
        sm[threadIdx.x] += t;
        __syncthreads();
    }
    if (threadIdx.x < nb) g_bsum[threadIdx.x] = sm[threadIdx.x] - v;  // exclusive
}

__global__ void k_scan3(int N) {
    int i = blockIdx.x * blockDim.x + threadIdx.x;
    if (i < N) g_rowstart[i] += g_bsum[i >> 10];
}

__global__ void k_fill(int E, int N) {
    int e = blockIdx.x * blockDim.x + threadIdx.x;
    if (e < E) {
        int s = g_src[e];
        int d = g_dst[e];
        if ((unsigned)d < (unsigned)N && (unsigned)s < (unsigned)N) {
            int p = atomicAdd(&g_cursor[d], 1);
            g_csr[g_rowstart[d] + p] = s;
        }
    }
}

// ---------------- layer-1 GEMM: 4 nodes/warp, fused dropout + dis prescale ------
// Output in permuted layout (pos 2l = col l, pos 2l+1 = col l+32).
__global__ void __launch_bounds__(256) k_gemm1(const float* __restrict__ X,
                                               const float* __restrict__ W1, int N) {
    __shared__ float  Wp[NFEAT][NHID];   // Wp[k][2l] = W1[k][l], Wp[k][2l+1] = W1[k][l+32]
    __shared__ float4 xs[8][NFEAT];      // xs[w][f] = dropout'd x for 4 nodes

    int tid = threadIdx.x, w = tid >> 5, l = tid & 31;
    for (int idx = tid; idx < NFEAT * NHID; idx += 256) {
        int k = idx >> 6, j = idx & 63;
        Wp[k][((j & 31) << 1) | (j >> 5)] = W1[idx];
    }

    int n0 = (blockIdx.x * 8 + w) * 4;
    float* xsf = (float*)&xs[w][0];
    if (n0 < N) {
#pragma unroll
        for (int i = 0; i < 16; i++) {
            int el = l + 32 * i;            // 0..511
            int m = el >> 7, f = el & 127;
            int n = n0 + m;
            float xv = 0.0f;
            if (n < N) {
                uint32_t e = (uint32_t)n * 128u + (uint32_t)f;
                float raw = X[(size_t)n * NFEAT + f] * 2.0f;
                xv = dropout_keep(e) ? raw : 0.0f;
            }
            xsf[f * 4 + m] = xv;
        }
    }
    __syncthreads();
    if (n0 >= N) return;

    float y00 = 0.f, y01 = 0.f, y10 = 0.f, y11 = 0.f;
    float y20 = 0.f, y21 = 0.f, y30 = 0.f, y31 = 0.f;
#pragma unroll 4
    for (int k = 0; k < NFEAT; k++) {
        float4 xv = xs[w][k];
        float2 wv = *(const float2*)&Wp[k][l << 1];
        y00 = fmaf(xv.x, wv.x, y00);  y01 = fmaf(xv.x, wv.y, y01);
        y10 = fmaf(xv.y, wv.x, y10);  y11 = fmaf(xv.y, wv.y, y11);
        y20 = fmaf(xv.z, wv.x, y20);  y21 = fmaf(xv.z, wv.y, y21);
        y30 = fmaf(xv.w, wv.x, y30);  y31 = fmaf(xv.w, wv.y, y31);
    }
    float2 o;
    if (n0 + 0 < N) { float dn = g_dis[n0];     o = make_float2(y00*dn, y01*dn); *(float2*)&g_xw[(size_t)(n0  )*NHID + 2*l] = o; }
    if (n0 + 1 < N) { float dn = g_dis[n0 + 1]; o = make_float2(y10*dn, y11*dn); *(float2*)&g_xw[(size_t)(n0+1)*NHID + 2*l] = o; }
    if (n0 + 2 < N) { float dn = g_dis[n0 + 2]; o = make_float2(y20*dn, y21*dn); *(float2*)&g_xw[(size_t)(n0+2)*NHID + 2*l] = o; }
    if (n0 + 3 < N) { float dn = g_dis[n0 + 3]; o = make_float2(y30*dn, y31*dn); *(float2*)&g_xw[(size_t)(n0+3)*NHID + 2*l] = o; }
}

// ---------------- layer-1 aggregation + bias + ReLU + layer-2 GEMM, fused -------
__global__ void __launch_bounds__(256) k_gather1(const float* __restrict__ b1,
                                                 const float* __restrict__ W2, int N) {
    __shared__ float W2s[NHID][64];   // cols 40..63 zero-padded
    int tid = threadIdx.x, l = tid & 31;
    for (int idx = tid; idx < NHID * 64; idx += 256) ((float*)W2s)[idx] = 0.0f;
    __syncthreads();
    for (int idx = tid; idx < NHID * NCLASS; idx += 256)
        W2s[idx / NCLASS][idx % NCLASS] = W2[idx];
    __syncthreads();

    int n = (blockIdx.x * 256 + tid) >> 5;
    if (n >= N) return;

    // permuted g_xw: lane l holds cols (l, l+32) as float2
    float2 acc = *(const float2*)&g_xw[(size_t)n * NHID + 2 * l];  // self-loop
    int beg = g_rowstart[n], cnt = g_cnt[n];
    const int* cs = g_csr + beg;
    for (int i = 0; i < cnt; i++) {
        int s = cs[i];
        float2 v = *(const float2*)&g_xw[(size_t)s * NHID + 2 * l];
        acc.x += v.x; acc.y += v.y;
    }
    float dn = g_dis[n];
    float h0 = fmaxf(fmaf(acc.x, dn, b1[l]),      0.0f);   // feature l
    float h1 = fmaxf(fmaf(acc.y, dn, b1[32 + l]), 0.0f);   // feature l+32

    // layer-2 GEMM via shfl broadcast
    float y0 = 0.f, y1 = 0.f;
#pragma unroll
    for (int k = 0; k < 32; k++) {
        float hk = __shfl_sync(0xffffffffu, h0, k);
        y0 = fmaf(hk, W2s[k][l], y0);
        y1 = fmaf(hk, W2s[k][32 + l], y1);
    }
#pragma unroll
    for (int k = 0; k < 32; k++) {
        float hk = __shfl_sync(0xffffffffu, h1, k);
        y0 = fmaf(hk, W2s[32 + k][l], y0);
        y1 = fmaf(hk, W2s[32 + k][32 + l], y1);
    }
    g_hw[(size_t)n * HWS + l] = y0 * dn;
    if (l < 8) g_hw[(size_t)n * HWS + 32 + l] = y1 * dn;
}

// ---------------- layer-2 aggregation + bias -> output --------------------------
__global__ void __launch_bounds__(256) k_gather2(const float* __restrict__ b2,
                                                 float* __restrict__ out, int N) {
    int n = (blockIdx.x * 256 + threadIdx.x) >> 5;
    int l = threadIdx.x & 31;
    if (n >= N) return;

    float a0 = g_hw[(size_t)n * HWS + l];                        // self-loop
    float a1 = (l < 8) ? g_hw[(size_t)n * HWS + 32 + l] : 0.0f;
    int beg = g_rowstart[n], cnt = g_cnt[n];
    const int* cs = g_csr + beg;
    for (int i = 0; i < cnt; i++) {
        int s = cs[i];
        a0 += g_hw[(size_t)s * HWS + l];
        if (l < 8) a1 += g_hw[(size_t)s * HWS + 32 + l];
    }
    float dn = g_dis[n];
    out[(size_t)n * NCLASS + l] = fmaf(a0, dn, b2[l]);
    if (l < 8) out[(size_t)n * NCLASS + 32 + l] = fmaf(a1, dn, b2[32 + l]);
}

// ---------------- launch ----------------
extern "C" void kernel_launch(void* const* d_in, const int* in_sizes, int n_in,
                              void* d_out, int out_size) {
    const float* X  = (const float*)d_in[0];
    const void*  ei = (const void*)d_in[1];
    const float* W1 = (const float*)d_in[2];
    const float* b1 = (const float*)d_in[3];
    const float* W2 = (const float*)d_in[4];
    const float* b2 = (const float*)d_in[5];
    float*       out = (float*)d_out;

    int N = in_sizes[0] / NFEAT;   // 100000
    int E = in_sizes[1] / 2;       // 1600000
    int nb = (N + 1023) / 1024;

    k_init <<<(N + 255) / 256, 256>>>(N);
    k_prep <<<(E + 255) / 256, 256>>>(ei, E, N);
    k_scan1<<<nb, 1024>>>(N);
    k_scan2<<<1, 128>>>(nb);
    k_scan3<<<(N + 1023) / 1024, 1024>>>(N);
    k_fill <<<(E + 255) / 256, 256>>>(E, N);

    k_gemm1  <<<(N + 31) / 32, 256>>>(X, W1, N);
    k_gather1<<<(N + 7) / 8, 256>>>(b1, W2, N);
    k_gather2<<<(N + 7) / 8, 256>>>(b2, out, N);
}

// round 6
// speedup vs baseline: 1.9062x; 1.0091x over previous
#include <cuda_runtime.h>
#include <stdint.h>

#define NNODES 100000
#define NEDGES 1600000
#define NFEAT  128
#define NHID   64
#define NCLASS 40
#define HWS    64   // padded row stride for g_hw (256B-aligned rows)

// ---------------- scratch (static device globals; no allocation) ----------------
__device__ int   g_cnt[NNODES];
__device__ int   g_cursor[NNODES];
__device__ int   g_rowstart[NNODES];
__device__ int   g_bsum[128];
__device__ int   g_csr[NEDGES];
__device__ float g_dis[NNODES];
// permuted layout: g_xw[n*64 + 2l] = col l, [n*64 + 2l+1] = col l+32 (UNscaled)
__device__ float g_xw[(size_t)NNODES * NHID];
__device__ float g_hw[(size_t)NNODES * HWS];   // dis[n] * (h @ W2), cols 0..39

// ---------------- threefry2x32, key = (0, 42) ----------------
__device__ __forceinline__ void threefry_0_42(uint32_t x0, uint32_t x1,
                                              uint32_t& o0, uint32_t& o1) {
    const uint32_t k0 = 0u, k1 = 42u;
    const uint32_t k2 = k0 ^ k1 ^ 0x1BD11BDAu;
    x0 += k0; x1 += k1;
#define TF_RND(R) { x0 += x1; x1 = (x1 << (R)) | (x1 >> (32 - (R))); x1 ^= x0; }
    TF_RND(13) TF_RND(15) TF_RND(26) TF_RND(6)   x0 += k1; x1 += k2 + 1u;
    TF_RND(17) TF_RND(29) TF_RND(16) TF_RND(24)  x0 += k2; x1 += k0 + 2u;
    TF_RND(13) TF_RND(15) TF_RND(26) TF_RND(6)   x0 += k0; x1 += k1 + 3u;
    TF_RND(17) TF_RND(29) TF_RND(16) TF_RND(24)  x0 += k1; x1 += k2 + 4u;
    TF_RND(13) TF_RND(15) TF_RND(26) TF_RND(6)   x0 += k2; x1 += k0 + 5u;
#undef TF_RND
    o0 = x0; o1 = x1;
}

// JAX threefry_partitionable bits32: bits = out0 ^ out1 of threefry(key,(hi,lo)); keep = MSB==0
__device__ __forceinline__ bool dropout_keep(uint32_t e) {
    uint32_t o0, o1;
    threefry_0_42(0u, e, o0, o1);
    return ((o0 ^ o1) & 0x80000000u) == 0u;
}

// ---------------- dtype sniff (int64 values < 2^32 -> all hi-words zero) --------
__device__ __forceinline__ int sniff_is64(const void* ei) {
    const unsigned long long* p = (const unsigned long long*)ei;
    unsigned long long acc = 0;
#pragma unroll
    for (int i = 0; i < 64; i++) acc |= (p[i] >> 32);
    return acc == 0ull;
}

// ---------------- histogram over dst half ----------------
__global__ void k_hist(const void* __restrict__ ei, int E, int N) {
    __shared__ int s_is64;
    if (threadIdx.x == 0) s_is64 = sniff_is64(ei);
    __syncthreads();
    int e = blockIdx.x * blockDim.x + threadIdx.x;
    if (e >= E) return;
    int d = s_is64 ? (int)((const long long*)ei)[(size_t)E + e]
                   : ((const int*)ei)[(size_t)E + e];
    if ((unsigned)d < (unsigned)N) atomicAdd(&g_cnt[d], 1);
}

// ---------------- block-local scan + dis ----------------
__global__ void k_scan1(int N) {
    __shared__ int sm[1024];
    int i = blockIdx.x * 1024 + threadIdx.x;
    int v = (i < N) ? g_cnt[i] : 0;
    if (i < N) g_dis[i] = rsqrtf((float)v + 1.0f);   // deg includes self-loop
    sm[threadIdx.x] = v;
    __syncthreads();
    for (int off = 1; off < 1024; off <<= 1) {
        int t = (threadIdx.x >= off) ? sm[threadIdx.x - off] : 0;
        __syncthreads();
        sm[threadIdx.x] += t;
        __syncthreads();
    }
    if (i < N) g_rowstart[i] = sm[threadIdx.x] - v;   // exclusive within block
    if (threadIdx.x == 1023) g_bsum[blockIdx.x] = sm[1023];
}

__global__ void k_scan2(int nb) {
    __shared__ int sm[128];
    int v = (threadIdx.x < nb) ? g_bsum[threadIdx.x] : 0;
    sm[threadIdx.x] = v;
    __syncthreads();
    for (int off = 1; off < 128; off <<= 1) {
        int t = (threadIdx.x >= off) ? sm[threadIdx.x - off] : 0;
        __syncthreads();
        sm[threadIdx.x] += t;
        __syncthreads();
    }
    if (threadIdx.x < nb) g_bsum[threadIdx.x] = sm[threadIdx.x] - v;  // exclusive
}

// ---------------- fill CSR (block offset folded in) ----------------
__global__ void k_fill(const void* __restrict__ ei, int E, int N) {
    __shared__ int s_is64;
    if (threadIdx.x == 0) s_is64 = sniff_is64(ei);
    __syncthreads();
    int e = blockIdx.x * blockDim.x + threadIdx.x;
    if (e >= E) return;
    int s, d;
    if (s_is64) {
        const long long* p = (const long long*)ei;
        s = (int)p[e];
        d = (int)p[(size_t)E + e];
    } else {
        const int* p = (const int*)ei;
        s = p[e];
        d = p[(size_t)E + e];
    }
    if ((unsigned)d < (unsigned)N && (unsigned)s < (unsigned)N) {
        int p = atomicAdd(&g_cursor[d], 1);
        g_csr[g_rowstart[d] + g_bsum[d >> 10] + p] = s;
    }
}

// ---------------- layer-1 GEMM: 4 nodes/warp, fused dropout (no dis needed) -----
__global__ void __launch_bounds__(256) k_gemm1(const float* __restrict__ X,
                                               const float* __restrict__ W1, int N) {
    __shared__ float  Wp[NFEAT][NHID];   // Wp[k][2l] = W1[k][l], Wp[k][2l+1] = W1[k][l+32]
    __shared__ float4 xs[8][NFEAT];      // xs[w][f] = dropout'd x for 4 nodes

    int tid = threadIdx.x, w = tid >> 5, l = tid & 31;
    for (int idx = tid; idx < NFEAT * NHID; idx += 256) {
        int k = idx >> 6, j = idx & 63;
        Wp[k][((j & 31) << 1) | (j >> 5)] = W1[idx];
    }

    int n0 = (blockIdx.x * 8 + w) * 4;
    float* xsf = (float*)&xs[w][0];
    if (n0 < N) {
#pragma unroll
        for (int i = 0; i < 16; i++) {
            int el = l + 32 * i;            // 0..511
            int m = el >> 7, f = el & 127;
            int n = n0 + m;
            float xv = 0.0f;
            if (n < N) {
                uint32_t e = (uint32_t)n * 128u + (uint32_t)f;
                float raw = X[(size_t)n * NFEAT + f] * 2.0f;
                xv = dropout_keep(e) ? raw : 0.0f;
            }
            xsf[f * 4 + m] = xv;
        }
    }
    __syncthreads();
    if (n0 >= N) return;

    float y00 = 0.f, y01 = 0.f, y10 = 0.f, y11 = 0.f;
    float y20 = 0.f, y21 = 0.f, y30 = 0.f, y31 = 0.f;
#pragma unroll 4
    for (int k = 0; k < NFEAT; k++) {
        float4 xv = xs[w][k];
        float2 wv = *(const float2*)&Wp[k][l << 1];
        y00 = fmaf(xv.x, wv.x, y00);  y01 = fmaf(xv.x, wv.y, y01);
        y10 = fmaf(xv.y, wv.x, y10);  y11 = fmaf(xv.y, wv.y, y11);
        y20 = fmaf(xv.z, wv.x, y20);  y21 = fmaf(xv.z, wv.y, y21);
        y30 = fmaf(xv.w, wv.x, y30);  y31 = fmaf(xv.w, wv.y, y31);
    }
    if (n0 + 0 < N) *(float2*)&g_xw[(size_t)(n0    )*NHID + 2*l] = make_float2(y00, y01);
    if (n0 + 1 < N) *(float2*)&g_xw[(size_t)(n0 + 1)*NHID + 2*l] = make_float2(y10, y11);
    if (n0 + 2 < N) *(float2*)&g_xw[(size_t)(n0 + 2)*NHID + 2*l] = make_float2(y20, y21);
    if (n0 + 3 < N) *(float2*)&g_xw[(size_t)(n0 + 3)*NHID + 2*l] = make_float2(y30, y31);
}

// ---------------- layer-1 aggregation + bias + ReLU + layer-2 GEMM, fused -------
__global__ void __launch_bounds__(256) k_gather1(const float* __restrict__ b1,
                                                 const float* __restrict__ W2, int N) {
    __shared__ float W2s[NHID][64];   // cols 40..63 zero-padded
    int tid = threadIdx.x, l = tid & 31;
    for (int idx = tid; idx < NHID * 64; idx += 256) ((float*)W2s)[idx] = 0.0f;
    __syncthreads();
    for (int idx = tid; idx < NHID * NCLASS; idx += 256)
        W2s[idx / NCLASS][idx % NCLASS] = W2[idx];
    __syncthreads();

    int n = (blockIdx.x * 256 + tid) >> 5;
    if (n >= N) return;

    float dn = g_dis[n];
    int cnt = g_cnt[n];
    const int* cs = g_csr + g_rowstart[n] + g_bsum[n >> 10];

    // self-loop term: dis[n] * xw[n]
    float2 v = *(const float2*)&g_xw[(size_t)n * NHID + 2 * l];
    float2 acc = make_float2(dn * v.x, dn * v.y);

    int i = 0;
    for (; i + 4 <= cnt; i += 4) {
        int s0 = cs[i], s1 = cs[i+1], s2 = cs[i+2], s3 = cs[i+3];
        float d0 = g_dis[s0], d1 = g_dis[s1], d2 = g_dis[s2], d3 = g_dis[s3];
        float2 v0 = *(const float2*)&g_xw[(size_t)s0 * NHID + 2 * l];
        float2 v1 = *(const float2*)&g_xw[(size_t)s1 * NHID + 2 * l];
        float2 v2 = *(const float2*)&g_xw[(size_t)s2 * NHID + 2 * l];
        float2 v3 = *(const float2*)&g_xw[(size_t)s3 * NHID + 2 * l];
        acc.x = fmaf(d0, v0.x, acc.x); acc.y = fmaf(d0, v0.y, acc.y);
        acc.x = fmaf(d1, v1.x, acc.x); acc.y = fmaf(d1, v1.y, acc.y);
        acc.x = fmaf(d2, v2.x, acc.x); acc.y = fmaf(d2, v2.y, acc.y);
        acc.x = fmaf(d3, v3.x, acc.x); acc.y = fmaf(d3, v3.y, acc.y);
    }
    for (; i < cnt; i++) {
        int s = cs[i];
        float ds = g_dis[s];
        float2 vv = *(const float2*)&g_xw[(size_t)s * NHID + 2 * l];
        acc.x = fmaf(ds, vv.x, acc.x); acc.y = fmaf(ds, vv.y, acc.y);
    }

    float h0 = fmaxf(fmaf(acc.x, dn, b1[l]),      0.0f);   // feature l
    float h1 = fmaxf(fmaf(acc.y, dn, b1[32 + l]), 0.0f);   // feature l+32

    // layer-2 GEMM via shfl broadcast
    float y0 = 0.f, y1 = 0.f;
#pragma unroll
    for (int k = 0; k < 32; k++) {
        float hk = __shfl_sync(0xffffffffu, h0, k);
        y0 = fmaf(hk, W2s[k][l], y0);
        y1 = fmaf(hk, W2s[k][32 + l], y1);
    }
#pragma unroll
    for (int k = 0; k < 32; k++) {
        float hk = __shfl_sync(0xffffffffu, h1, k);
        y0 = fmaf(hk, W2s[32 + k][l], y0);
        y1 = fmaf(hk, W2s[32 + k][32 + l], y1);
    }
    g_hw[(size_t)n * HWS + l] = y0 * dn;
    if (l < 8) g_hw[(size_t)n * HWS + 32 + l] = y1 * dn;
}

// ---------------- layer-2 aggregation + bias -> output --------------------------
__global__ void __launch_bounds__(256) k_gather2(const float* __restrict__ b2,
                                                 float* __restrict__ out, int N) {
    int n = (blockIdx.x * 256 + threadIdx.x) >> 5;
    int l = threadIdx.x & 31;
    if (n >= N) return;

    float a0 = g_hw[(size_t)n * HWS + l];                        // self-loop
    float a1 = (l < 8) ? g_hw[(size_t)n * HWS + 32 + l] : 0.0f;
    int cnt = g_cnt[n];
    const int* cs = g_csr + g_rowstart[n] + g_bsum[n >> 10];

    int i = 0;
    for (; i + 4 <= cnt; i += 4) {
        int s0 = cs[i], s1 = cs[i+1], s2 = cs[i+2], s3 = cs[i+3];
        float b0 = g_hw[(size_t)s0 * HWS + l];
        float b1v = g_hw[(size_t)s1 * HWS + l];
        float b2v = g_hw[(size_t)s2 * HWS + l];
        float b3 = g_hw[(size_t)s3 * HWS + l];
        a0 += (b0 + b1v) + (b2v + b3);
        if (l < 8) {
            float c0 = g_hw[(size_t)s0 * HWS + 32 + l];
            float c1 = g_hw[(size_t)s1 * HWS + 32 + l];
            float c2 = g_hw[(size_t)s2 * HWS + 32 + l];
            float c3 = g_hw[(size_t)s3 * HWS + 32 + l];
            a1 += (c0 + c1) + (c2 + c3);
        }
    }
    for (; i < cnt; i++) {
        int s = cs[i];
        a0 += g_hw[(size_t)s * HWS + l];
        if (l < 8) a1 += g_hw[(size_t)s * HWS + 32 + l];
    }
    float dn = g_dis[n];
    out[(size_t)n * NCLASS + l] = fmaf(a0, dn, b2[l]);
    if (l < 8) out[(size_t)n * NCLASS + 32 + l] = fmaf(a1, dn, b2[32 + l]);
}

// ---------------- streams/events for captured fork (static init: mem delta = 0) -
struct ForkCtx {
    cudaStream_t s1;
    cudaEvent_t evA, evB;
    ForkCtx() {
        cudaStreamCreateWithFlags(&s1, cudaStreamNonBlocking);
        cudaEventCreateWithFlags(&evA, cudaEventDisableTiming);
        cudaEventCreateWithFlags(&evB, cudaEventDisableTiming);
    }
};
static ForkCtx g_fork;

// ---------------- launch ----------------
extern "C" void kernel_launch(void* const* d_in, const int* in_sizes, int n_in,
                              void* d_out, int out_size) {
    const float* X  = (const float*)d_in[0];
    const void*  ei = (const void*)d_in[1];
    const float* W1 = (const float*)d_in[2];
    const float* b1 = (const float*)d_in[3];
    const float* W2 = (const float*)d_in[4];
    const float* b2 = (const float*)d_in[5];
    float*       out = (float*)d_out;

    int N = in_sizes[0] / NFEAT;   // 100000
    int E = in_sizes[1] / 2;       // 1600000
    int nb = (N + 1023) / 1024;

    cudaStream_t s0 = cudaStreamPerThread;
    cudaStream_t s1 = g_fork.s1;

    // fork: gemm1 runs concurrently with the CSR chain
    cudaEventRecord(g_fork.evA, s0);
    cudaStreamWaitEvent(s1, g_fork.evA, 0);
    k_gemm1<<<(N + 31) / 32, 256, 0, s1>>>(X, W1, N);
    cudaEventRecord(g_fork.evB, s1);

    // CSR chain on s0
    void* cnt_addr = nullptr; void* cur_addr = nullptr;
    cudaGetSymbolAddress(&cnt_addr, g_cnt);
    cudaGetSymbolAddress(&cur_addr, g_cursor);
    cudaMemsetAsync(cnt_addr, 0, (size_t)N * sizeof(int), s0);
    cudaMemsetAsync(cur_addr, 0, (size_t)N * sizeof(int), s0);
    k_hist <<<(E + 255) / 256, 256, 0, s0>>>(ei, E, N);
    k_scan1<<<nb, 1024, 0, s0>>>(N);
    k_scan2<<<1, 128, 0, s0>>>(nb);
    k_fill <<<(E + 255) / 256, 256, 0, s0>>>(ei, E, N);

    // join, then fused aggregations
    cudaStreamWaitEvent(s0, g_fork.evB, 0);
    k_gather1<<<(N + 7) / 8, 256, 0, s0>>>(b1, W2, N);
    k_gather2<<<(N + 7) / 8, 256, 0, s0>>>(b2, out, N);
}

// round 7
// speedup vs baseline: 1.9213x; 1.0079x over previous
#include <cuda_runtime.h>
#include <stdint.h>

#define NNODES 100000
#define NEDGES 1600000
#define NFEAT  128
#define NHID   64
#define NCLASS 40
#define HWS    64   // padded row stride for g_hw (256B-aligned rows)

// ---------------- scratch (static device globals; no allocation) ----------------
// zeroed region: [0,N)=cnt, [N,2N)=cursor, [2N]=scan ticket
__device__ int   g_zeroed[2 * NNODES + 1];
__device__ int   g_rowstart[NNODES];
__device__ int   g_bsum[128];
__device__ int   g_csr[NEDGES];
__device__ float g_dis[NNODES];
// permuted layout: g_xw[n*64 + 2l] = col l, [n*64 + 2l+1] = col l+32 (UNscaled)
__device__ float g_xw[(size_t)NNODES * NHID];
__device__ float g_hw[(size_t)NNODES * HWS];   // dis[n] * (h @ W2), cols 0..39

// ---------------- threefry2x32, key = (0, 42) ----------------
__device__ __forceinline__ void threefry_0_42(uint32_t x0, uint32_t x1,
                                              uint32_t& o0, uint32_t& o1) {
    const uint32_t k0 = 0u, k1 = 42u;
    const uint32_t k2 = k0 ^ k1 ^ 0x1BD11BDAu;
    x0 += k0; x1 += k1;
#define TF_RND(R) { x0 += x1; x1 = (x1 << (R)) | (x1 >> (32 - (R))); x1 ^= x0; }
    TF_RND(13) TF_RND(15) TF_RND(26) TF_RND(6)   x0 += k1; x1 += k2 + 1u;
    TF_RND(17) TF_RND(29) TF_RND(16) TF_RND(24)  x0 += k2; x1 += k0 + 2u;
    TF_RND(13) TF_RND(15) TF_RND(26) TF_RND(6)   x0 += k0; x1 += k1 + 3u;
    TF_RND(17) TF_RND(29) TF_RND(16) TF_RND(24)  x0 += k1; x1 += k2 + 4u;
    TF_RND(13) TF_RND(15) TF_RND(26) TF_RND(6)   x0 += k2; x1 += k0 + 5u;
#undef TF_RND
    o0 = x0; o1 = x1;
}

// JAX threefry_partitionable bits32: bits = out0 ^ out1 of threefry(key,(hi,lo)); keep = MSB==0
__device__ __forceinline__ bool dropout_keep(uint32_t e) {
    uint32_t o0, o1;
    threefry_0_42(0u, e, o0, o1);
    return ((o0 ^ o1) & 0x80000000u) == 0u;
}

// ---------------- dtype sniff (int64 values < 2^32 -> all hi-words zero) --------
__device__ __forceinline__ int sniff_is64(const void* ei) {
    const unsigned long long* p = (const unsigned long long*)ei;
    unsigned long long acc = 0;
#pragma unroll
    for (int i = 0; i < 64; i++) acc |= (p[i] >> 32);
    return acc == 0ull;
}

// ---------------- histogram over dst half (2 edges / thread) ----------------
__global__ void __launch_bounds__(256) k_hist(const void* __restrict__ ei, int E, int N) {
    __shared__ int s_is64;
    if (threadIdx.x == 0) s_is64 = sniff_is64(ei);
    __syncthreads();
    int e0 = (blockIdx.x * 256 + threadIdx.x) * 2;
    if (e0 >= E) return;
    int d0, d1;
    if (s_is64) {
        const longlong2* pd = (const longlong2*)((const long long*)ei + E);
        longlong2 dv = pd[e0 >> 1];
        d0 = (int)dv.x; d1 = (int)dv.y;
    } else {
        const int2* pd = (const int2*)((const int*)ei + E);
        int2 dv = pd[e0 >> 1];
        d0 = dv.x; d1 = dv.y;
    }
    if ((unsigned)d0 < (unsigned)N) atomicAdd(&g_zeroed[d0], 1);
    if (e0 + 1 < E && (unsigned)d1 < (unsigned)N) atomicAdd(&g_zeroed[d1], 1);
}

// ---------------- scan (warp-shuffle) + dis + decoupled final block scan --------
__global__ void __launch_bounds__(1024) k_scan1(int N) {
    __shared__ int wsum[32];
    __shared__ int woff[32];
    __shared__ int s_total;
    __shared__ int s_last;
    __shared__ int sm2[128];

    int tid = threadIdx.x;
    int i = blockIdx.x * 1024 + tid;
    int lane = tid & 31, wid = tid >> 5;

    int v = (i < N) ? g_zeroed[i] : 0;           // cnt
    if (i < N) g_dis[i] = rsqrtf((float)v + 1.0f);

    int inc = v;
#pragma unroll
    for (int o = 1; o < 32; o <<= 1) {
        int t = __shfl_up_sync(0xffffffffu, inc, o);
        if (lane >= o) inc += t;
    }
    if (lane == 31) wsum[wid] = inc;
    __syncthreads();
    if (wid == 0) {
        int w = wsum[lane];
        int winc = w;
#pragma unroll
        for (int o = 1; o < 32; o <<= 1) {
            int t = __shfl_up_sync(0xffffffffu, winc, o);
            if (lane >= o) winc += t;
        }
        woff[lane] = winc - w;                   // exclusive warp offsets
        if (lane == 31) s_total = winc;          // block total
    }
    __syncthreads();
    if (i < N) g_rowstart[i] = inc - v + woff[wid];

    // decoupled: last block to finish converts g_bsum to exclusive offsets
    if (tid == 0) {
        g_bsum[blockIdx.x] = s_total;
        __threadfence();
        int t = atomicAdd(&g_zeroed[2 * NNODES], 1);
        s_last = (t == (int)gridDim.x - 1);
    }
    __syncthreads();
    if (s_last) {
        __threadfence();
        int nb = gridDim.x;
        int val = 0;
        if (tid < 128) {
            val = (tid < nb) ? ((volatile int*)g_bsum)[tid] : 0;
            sm2[tid] = val;
        }
        __syncthreads();
        for (int o = 1; o < 128; o <<= 1) {
            int t = 0;
            if (tid < 128 && tid >= o) t = sm2[tid - o];
            __syncthreads();
            if (tid < 128) sm2[tid] += t;
            __syncthreads();
        }
        if (tid < nb) g_bsum[tid] = sm2[tid] - val;   // exclusive
    }
}

// ---------------- fill CSR (2 edges / thread, block offset folded in) -----------
__global__ void __launch_bounds__(256) k_fill(const void* __restrict__ ei, int E, int N) {
    __shared__ int s_is64;
    if (threadIdx.x == 0) s_is64 = sniff_is64(ei);
    __syncthreads();
    int e0 = (blockIdx.x * 256 + threadIdx.x) * 2;
    if (e0 >= E) return;
    int s0, d0, s1, d1;
    if (s_is64) {
        const longlong2* ps = (const longlong2*)ei;
        const longlong2* pd = (const longlong2*)((const long long*)ei + E);
        longlong2 sv = ps[e0 >> 1], dv = pd[e0 >> 1];
        s0 = (int)sv.x; s1 = (int)sv.y; d0 = (int)dv.x; d1 = (int)dv.y;
    } else {
        const int2* ps = (const int2*)ei;
        const int2* pd = (const int2*)((const int*)ei + E);
        int2 sv = ps[e0 >> 1], dv = pd[e0 >> 1];
        s0 = sv.x; s1 = sv.y; d0 = dv.x; d1 = dv.y;
    }
    if ((unsigned)d0 < (unsigned)N && (unsigned)s0 < (unsigned)N) {
        int p = atomicAdd(&g_zeroed[NNODES + d0], 1);
        g_csr[g_rowstart[d0] + g_bsum[d0 >> 10] + p] = s0;
    }
    if (e0 + 1 < E && (unsigned)d1 < (unsigned)N && (unsigned)s1 < (unsigned)N) {
        int p = atomicAdd(&g_zeroed[NNODES + d1], 1);
        g_csr[g_rowstart[d1] + g_bsum[d1 >> 10] + p] = s1;
    }
}

// ---------------- layer-1 GEMM: 4 nodes/warp, fused dropout -----
__global__ void __launch_bounds__(256) k_gemm1(const float* __restrict__ X,
                                               const float* __restrict__ W1, int N) {
    __shared__ float  Wp[NFEAT][NHID];   // Wp[k][2l] = W1[k][l], Wp[k][2l+1] = W1[k][l+32]
    __shared__ float4 xs[8][NFEAT];      // xs[w][f] = dropout'd x for 4 nodes

    int tid = threadIdx.x, w = tid >> 5, l = tid & 31;
    for (int idx = tid; idx < NFEAT * NHID; idx += 256) {
        int k = idx >> 6, j = idx & 63;
        Wp[k][((j & 31) << 1) | (j >> 5)] = W1[idx];
    }

    int n0 = (blockIdx.x * 8 + w) * 4;
    float* xsf = (float*)&xs[w][0];
    if (n0 < N) {
#pragma unroll
        for (int i = 0; i < 16; i++) {
            int el = l + 32 * i;            // 0..511
            int m = el >> 7, f = el & 127;
            int n = n0 + m;
            float xv = 0.0f;
            if (n < N) {
                uint32_t e = (uint32_t)n * 128u + (uint32_t)f;
                float raw = X[(size_t)n * NFEAT + f] * 2.0f;
                xv = dropout_keep(e) ? raw : 0.0f;
            }
            xsf[f * 4 + m] = xv;
        }
    }
    __syncthreads();
    if (n0 >= N) return;

    float y00 = 0.f, y01 = 0.f, y10 = 0.f, y11 = 0.f;
    float y20 = 0.f, y21 = 0.f, y30 = 0.f, y31 = 0.f;
#pragma unroll 4
    for (int k = 0; k < NFEAT; k++) {
        float4 xv = xs[w][k];
        float2 wv = *(const float2*)&Wp[k][l << 1];
        y00 = fmaf(xv.x, wv.x, y00);  y01 = fmaf(xv.x, wv.y, y01);
        y10 = fmaf(xv.y, wv.x, y10);  y11 = fmaf(xv.y, wv.y, y11);
        y20 = fmaf(xv.z, wv.x, y20);  y21 = fmaf(xv.z, wv.y, y21);
        y30 = fmaf(xv.w, wv.x, y30);  y31 = fmaf(xv.w, wv.y, y31);
    }
    if (n0 + 0 < N) *(float2*)&g_xw[(size_t)(n0    )*NHID + 2*l] = make_float2(y00, y01);
    if (n0 + 1 < N) *(float2*)&g_xw[(size_t)(n0 + 1)*NHID + 2*l] = make_float2(y10, y11);
    if (n0 + 2 < N) *(float2*)&g_xw[(size_t)(n0 + 2)*NHID + 2*l] = make_float2(y20, y21);
    if (n0 + 3 < N) *(float2*)&g_xw[(size_t)(n0 + 3)*NHID + 2*l] = make_float2(y30, y31);
}

// ---------------- layer-1 aggregation + bias + ReLU + layer-2 GEMM, fused -------
__global__ void __launch_bounds__(256) k_gather1(const float* __restrict__ b1,
                                                 const float* __restrict__ W2, int N) {
    __shared__ float W2s[NHID][64];   // cols 40..63 zero-padded
    int tid = threadIdx.x, l = tid & 31;
    for (int idx = tid; idx < NHID * 64; idx += 256) ((float*)W2s)[idx] = 0.0f;
    __syncthreads();
    for (int idx = tid; idx < NHID * NCLASS; idx += 256)
        W2s[idx / NCLASS][idx % NCLASS] = W2[idx];
    __syncthreads();

    int n = (blockIdx.x * 256 + tid) >> 5;
    if (n >= N) return;

    float dn = g_dis[n];
    int cnt = g_zeroed[n];
    const int* cs = g_csr + g_rowstart[n] + g_bsum[n >> 10];

    // self-loop term: dis[n] * xw[n]
    float2 v = *(const float2*)&g_xw[(size_t)n * NHID + 2 * l];
    float2 acc = make_float2(dn * v.x, dn * v.y);

    int i = 0;
    for (; i + 4 <= cnt; i += 4) {
        int s0 = cs[i], s1 = cs[i+1], s2 = cs[i+2], s3 = cs[i+3];
        float d0 = g_dis[s0], d1 = g_dis[s1], d2 = g_dis[s2], d3 = g_dis[s3];
        float2 v0 = *(const float2*)&g_xw[(size_t)s0 * NHID + 2 * l];
        float2 v1 = *(const float2*)&g_xw[(size_t)s1 * NHID + 2 * l];
        float2 v2 = *(const float2*)&g_xw[(size_t)s2 * NHID + 2 * l];
        float2 v3 = *(const float2*)&g_xw[(size_t)s3 * NHID + 2 * l];
        acc.x = fmaf(d0, v0.x, acc.x); acc.y = fmaf(d0, v0.y, acc.y);
        acc.x = fmaf(d1, v1.x, acc.x); acc.y = fmaf(d1, v1.y, acc.y);
        acc.x = fmaf(d2, v2.x, acc.x); acc.y = fmaf(d2, v2.y, acc.y);
        acc.x = fmaf(d3, v3.x, acc.x); acc.y = fmaf(d3, v3.y, acc.y);
    }
    for (; i < cnt; i++) {
        int s = cs[i];
        float ds = g_dis[s];
        float2 vv = *(const float2*)&g_xw[(size_t)s * NHID + 2 * l];
        acc.x = fmaf(ds, vv.x, acc.x); acc.y = fmaf(ds, vv.y, acc.y);
    }

    float h0 = fmaxf(fmaf(acc.x, dn, b1[l]),      0.0f);   // feature l
    float h1 = fmaxf(fmaf(acc.y, dn, b1[32 + l]), 0.0f);   // feature l+32

    // layer-2 GEMM via shfl broadcast
    float y0 = 0.f, y1 = 0.f;
#pragma unroll
    for (int k = 0; k < 32; k++) {
        float hk = __shfl_sync(0xffffffffu, h0, k);
        y0 = fmaf(hk, W2s[k][l], y0);
        y1 = fmaf(hk, W2s[k][32 + l], y1);
    }
#pragma unroll
    for (int k = 0; k < 32; k++) {
        float hk = __shfl_sync(0xffffffffu, h1, k);
        y0 = fmaf(hk, W2s[32 + k][l], y0);
        y1 = fmaf(hk, W2s[32 + k][32 + l], y1);
    }
    g_hw[(size_t)n * HWS + l] = y0 * dn;
    if (l < 8) g_hw[(size_t)n * HWS + 32 + l] = y1 * dn;
}

// ---------------- layer-2 aggregation + bias -> output --------------------------
__global__ void __launch_bounds__(256) k_gather2(const float* __restrict__ b2,
                                                 float* __restrict__ out, int N) {
    int n = (blockIdx.x * 256 + threadIdx.x) >> 5;
    int l = threadIdx.x & 31;
    if (n >= N) return;

    float a0 = g_hw[(size_t)n * HWS + l];                        // self-loop
    float a1 = (l < 8) ? g_hw[(size_t)n * HWS + 32 + l] : 0.0f;
    int cnt = g_zeroed[n];
    const int* cs = g_csr + g_rowstart[n] + g_bsum[n >> 10];

    int i = 0;
    for (; i + 4 <= cnt; i += 4) {
        int s0 = cs[i], s1 = cs[i+1], s2 = cs[i+2], s3 = cs[i+3];
        float b0 = g_hw[(size_t)s0 * HWS + l];
        float b1v = g_hw[(size_t)s1 * HWS + l];
        float b2v = g_hw[(size_t)s2 * HWS + l];
        float b3 = g_hw[(size_t)s3 * HWS + l];
        a0 += (b0 + b1v) + (b2v + b3);
        if (l < 8) {
            float c0 = g_hw[(size_t)s0 * HWS + 32 + l];
            float c1 = g_hw[(size_t)s1 * HWS + 32 + l];
            float c2 = g_hw[(size_t)s2 * HWS + 32 + l];
            float c3 = g_hw[(size_t)s3 * HWS + 32 + l];
            a1 += (c0 + c1) + (c2 + c3);
        }
    }
    for (; i < cnt; i++) {
        int s = cs[i];
        a0 += g_hw[(size_t)s * HWS + l];
        if (l < 8) a1 += g_hw[(size_t)s * HWS + 32 + l];
    }
    float dn = g_dis[n];
    out[(size_t)n * NCLASS + l] = fmaf(a0, dn, b2[l]);
    if (l < 8) out[(size_t)n * NCLASS + 32 + l] = fmaf(a1, dn, b2[32 + l]);
}

// ---------------- streams/events for captured fork (static init: mem delta = 0) -
struct ForkCtx {
    cudaStream_t s1;
    cudaEvent_t evA, evB;
    ForkCtx() {
        cudaStreamCreateWithFlags(&s1, cudaStreamNonBlocking);
        cudaEventCreateWithFlags(&evA, cudaEventDisableTiming);
        cudaEventCreateWithFlags(&evB, cudaEventDisableTiming);
    }
};
static ForkCtx g_fork;

// ---------------- launch ----------------
extern "C" void kernel_launch(void* const* d_in, const int* in_sizes, int n_in,
                              void* d_out, int out_size) {
    const float* X  = (const float*)d_in[0];
    const void*  ei = (const void*)d_in[1];
    const float* W1 = (const float*)d_in[2];
    const float* b1 = (const float*)d_in[3];
    const float* W2 = (const float*)d_in[4];
    const float* b2 = (const float*)d_in[5];
    float*       out = (float*)d_out;

    int N = in_sizes[0] / NFEAT;   // 100000
    int E = in_sizes[1] / 2;       // 1600000
    int nb = (N + 1023) / 1024;
    int eb2 = (E / 2 + 255) / 256; // 2 edges per thread

    cudaStream_t s0 = cudaStreamPerThread;
    cudaStream_t s1 = g_fork.s1;

    // fork: gemm1 runs concurrently with the CSR chain
    cudaEventRecord(g_fork.evA, s0);
    cudaStreamWaitEvent(s1, g_fork.evA, 0);
    k_gemm1<<<(N + 31) / 32, 256, 0, s1>>>(X, W1, N);
    cudaEventRecord(g_fork.evB, s1);

    // CSR chain on s0
    void* z_addr = nullptr;
    cudaGetSymbolAddress(&z_addr, g_zeroed);
    cudaMemsetAsync(z_addr, 0, (size_t)(2 * NNODES + 1) * sizeof(int), s0);
    k_hist <<<eb2, 256, 0, s0>>>(ei, E, N);
    k_scan1<<<nb, 1024, 0, s0>>>(N);
    k_fill <<<eb2, 256, 0, s0>>>(ei, E, N);

    // join, then fused aggregations
    cudaStreamWaitEvent(s0, g_fork.evB, 0);
    k_gather1<<<(N + 7) / 8, 256, 0, s0>>>(b1, W2, N);
    k_gather2<<<(N + 7) / 8, 256, 0, s0>>>(b2, out, N);
}

// round 8
// speedup vs baseline: 2.2468x; 1.1694x over previous
#include <cuda_runtime.h>
#include <cuda_fp16.h>
#include <stdint.h>

#define NNODES 100000
#define NEDGES 1600000
#define NFEAT  128
#define NHID   64
#define NCLASS 40

// ---------------- scratch (static device globals; no allocation) ----------------
// zeroed region: [0,N)=cnt, [N,2N)=cursor, [2N]=scan ticket
__device__ int     g_zeroed[2 * NNODES + 1];
__device__ int     g_rowstart[NNODES];
__device__ int     g_bsum[128];
__device__ int     g_csr[NEDGES];
__device__ float   g_dis[NNODES];
// fp16 permuted: g_xw[n*32+l] = half2(col l, col l+32) of x@W1 (unscaled)
__device__ __half2 g_xw[(size_t)NNODES * 32];
__device__ float   g_h[(size_t)NNODES * NHID];   // relu(agg1+b1), plain layout
__device__ __half  g_hw[(size_t)NNODES * 64];    // dis[n]*(h@W2), cols 0..39, 128B rows

// ---------------- threefry2x32, key = (0, 42) ----------------
__device__ __forceinline__ void threefry_0_42(uint32_t x0, uint32_t x1,
                                              uint32_t& o0, uint32_t& o1) {
    const uint32_t k0 = 0u, k1 = 42u;
    const uint32_t k2 = k0 ^ k1 ^ 0x1BD11BDAu;
    x0 += k0; x1 += k1;
#define TF_RND(R) { x0 += x1; x1 = (x1 << (R)) | (x1 >> (32 - (R))); x1 ^= x0; }
    TF_RND(13) TF_RND(15) TF_RND(26) TF_RND(6)   x0 += k1; x1 += k2 + 1u;
    TF_RND(17) TF_RND(29) TF_RND(16) TF_RND(24)  x0 += k2; x1 += k0 + 2u;
    TF_RND(13) TF_RND(15) TF_RND(26) TF_RND(6)   x0 += k0; x1 += k1 + 3u;
    TF_RND(17) TF_RND(29) TF_RND(16) TF_RND(24)  x0 += k1; x1 += k2 + 4u;
    TF_RND(13) TF_RND(15) TF_RND(26) TF_RND(6)   x0 += k2; x1 += k0 + 5u;
#undef TF_RND
    o0 = x0; o1 = x1;
}

// JAX threefry_partitionable bits32: bits = out0 ^ out1; keep = MSB==0
__device__ __forceinline__ bool dropout_keep(uint32_t e) {
    uint32_t o0, o1;
    threefry_0_42(0u, e, o0, o1);
    return ((o0 ^ o1) & 0x80000000u) == 0u;
}

// ---------------- dtype sniff (int64 values < 2^32 -> all hi-words zero) --------
__device__ __forceinline__ int sniff_is64(const void* ei) {
    const unsigned long long* p = (const unsigned long long*)ei;
    unsigned long long acc = 0;
#pragma unroll
    for (int i = 0; i < 64; i++) acc |= (p[i] >> 32);
    return acc == 0ull;
}

// ---------------- histogram over dst half (2 edges / thread) ----------------
__global__ void __launch_bounds__(256) k_hist(const void* __restrict__ ei, int E, int N) {
    __shared__ int s_is64;
    if (threadIdx.x == 0) s_is64 = sniff_is64(ei);
    __syncthreads();
    int e0 = (blockIdx.x * 256 + threadIdx.x) * 2;
    if (e0 >= E) return;
    int d0, d1;
    if (s_is64) {
        const longlong2* pd = (const longlong2*)((const long long*)ei + E);
        longlong2 dv = pd[e0 >> 1];
        d0 = (int)dv.x; d1 = (int)dv.y;
    } else {
        const int2* pd = (const int2*)((const int*)ei + E);
        int2 dv = pd[e0 >> 1];
        d0 = dv.x; d1 = dv.y;
    }
    if ((unsigned)d0 < (unsigned)N) atomicAdd(&g_zeroed[d0], 1);
    if (e0 + 1 < E && (unsigned)d1 < (unsigned)N) atomicAdd(&g_zeroed[d1], 1);
}

// ---------------- scan (warp-shuffle) + dis + decoupled final block scan --------
__global__ void __launch_bounds__(1024) k_scan1(int N) {
    __shared__ int wsum[32];
    __shared__ int woff[32];
    __shared__ int s_total;
    __shared__ int s_last;
    __shared__ int sm2[128];

    int tid = threadIdx.x;
    int i = blockIdx.x * 1024 + tid;
    int lane = tid & 31, wid = tid >> 5;

    int v = (i < N) ? g_zeroed[i] : 0;           // cnt
    if (i < N) g_dis[i] = rsqrtf((float)v + 1.0f);

    int inc = v;
#pragma unroll
    for (int o = 1; o < 32; o <<= 1) {
        int t = __shfl_up_sync(0xffffffffu, inc, o);
        if (lane >= o) inc += t;
    }
    if (lane == 31) wsum[wid] = inc;
    __syncthreads();
    if (wid == 0) {
        int w = wsum[lane];
        int winc = w;
#pragma unroll
        for (int o = 1; o < 32; o <<= 1) {
            int t = __shfl_up_sync(0xffffffffu, winc, o);
            if (lane >= o) winc += t;
        }
        woff[lane] = winc - w;
        if (lane == 31) s_total = winc;
    }
    __syncthreads();
    if (i < N) g_rowstart[i] = inc - v + woff[wid];

    if (tid == 0) {
        g_bsum[blockIdx.x] = s_total;
        __threadfence();
        int t = atomicAdd(&g_zeroed[2 * NNODES], 1);
        s_last = (t == (int)gridDim.x - 1);
    }
    __syncthreads();
    if (s_last) {
        __threadfence();
        int nb = gridDim.x;
        int val = 0;
        if (tid < 128) {
            val = (tid < nb) ? ((volatile int*)g_bsum)[tid] : 0;
            sm2[tid] = val;
        }
        __syncthreads();
        for (int o = 1; o < 128; o <<= 1) {
            int t = 0;
            if (tid < 128 && tid >= o) t = sm2[tid - o];
            __syncthreads();
            if (tid < 128) sm2[tid] += t;
            __syncthreads();
        }
        if (tid < nb) g_bsum[tid] = sm2[tid] - val;
    }
}

// ---------------- fill CSR (2 edges / thread, block offset folded in) -----------
__global__ void __launch_bounds__(256) k_fill(const void* __restrict__ ei, int E, int N) {
    __shared__ int s_is64;
    if (threadIdx.x == 0) s_is64 = sniff_is64(ei);
    __syncthreads();
    int e0 = (blockIdx.x * 256 + threadIdx.x) * 2;
    if (e0 >= E) return;
    int s0, d0, s1, d1;
    if (s_is64) {
        const longlong2* ps = (const longlong2*)ei;
        const longlong2* pd = (const longlong2*)((const long long*)ei + E);
        longlong2 sv = ps[e0 >> 1], dv = pd[e0 >> 1];
        s0 = (int)sv.x; s1 = (int)sv.y; d0 = (int)dv.x; d1 = (int)dv.y;
    } else {
        const int2* ps = (const int2*)ei;
        const int2* pd = (const int2*)((const int*)ei + E);
        int2 sv = ps[e0 >> 1], dv = pd[e0 >> 1];
        s0 = sv.x; s1 = sv.y; d0 = dv.x; d1 = dv.y;
    }
    if ((unsigned)d0 < (unsigned)N && (unsigned)s0 < (unsigned)N) {
        int p = atomicAdd(&g_zeroed[NNODES + d0], 1);
        g_csr[g_rowstart[d0] + g_bsum[d0 >> 10] + p] = s0;
    }
    if (e0 + 1 < E && (unsigned)d1 < (unsigned)N && (unsigned)s1 < (unsigned)N) {
        int p = atomicAdd(&g_zeroed[NNODES + d1], 1);
        g_csr[g_rowstart[d1] + g_bsum[d1 >> 10] + p] = s1;
    }
}

// ---------------- layer-1 GEMM: 4 nodes/warp, fused dropout, fp16 out -----------
__global__ void __launch_bounds__(256) k_gemm1(const float* __restrict__ X,
                                               const float* __restrict__ W1, int N) {
    __shared__ float  Wp[NFEAT][NHID];   // Wp[k][2l] = W1[k][l], Wp[k][2l+1] = W1[k][l+32]
    __shared__ float4 xs[8][NFEAT];

    int tid = threadIdx.x, w = tid >> 5, l = tid & 31;
    for (int idx = tid; idx < NFEAT * NHID; idx += 256) {
        int k = idx >> 6, j = idx & 63;
        Wp[k][((j & 31) << 1) | (j >> 5)] = W1[idx];
    }

    int n0 = (blockIdx.x * 8 + w) * 4;
    float* xsf = (float*)&xs[w][0];
    if (n0 < N) {
#pragma unroll
        for (int i = 0; i < 16; i++) {
            int el = l + 32 * i;
            int m = el >> 7, f = el & 127;
            int n = n0 + m;
            float xv = 0.0f;
            if (n < N) {
                uint32_t e = (uint32_t)n * 128u + (uint32_t)f;
                float raw = X[(size_t)n * NFEAT + f] * 2.0f;
                xv = dropout_keep(e) ? raw : 0.0f;
            }
            xsf[f * 4 + m] = xv;
        }
    }
    __syncthreads();
    if (n0 >= N) return;

    float y00 = 0.f, y01 = 0.f, y10 = 0.f, y11 = 0.f;
    float y20 = 0.f, y21 = 0.f, y30 = 0.f, y31 = 0.f;
#pragma unroll 4
    for (int k = 0; k < NFEAT; k++) {
        float4 xv = xs[w][k];
        float2 wv = *(const float2*)&Wp[k][l << 1];
        y00 = fmaf(xv.x, wv.x, y00);  y01 = fmaf(xv.x, wv.y, y01);
        y10 = fmaf(xv.y, wv.x, y10);  y11 = fmaf(xv.y, wv.y, y11);
        y20 = fmaf(xv.z, wv.x, y20);  y21 = fmaf(xv.z, wv.y, y21);
        y30 = fmaf(xv.w, wv.x, y30);  y31 = fmaf(xv.w, wv.y, y31);
    }
    if (n0 + 0 < N) g_xw[(size_t)(n0    ) * 32 + l] = __floats2half2_rn(y00, y01);
    if (n0 + 1 < N) g_xw[(size_t)(n0 + 1) * 32 + l] = __floats2half2_rn(y10, y11);
    if (n0 + 2 < N) g_xw[(size_t)(n0 + 2) * 32 + l] = __floats2half2_rn(y20, y21);
    if (n0 + 3 < N) g_xw[(size_t)(n0 + 3) * 32 + l] = __floats2half2_rn(y30, y31);
}

// ---------------- layer-1 aggregation + bias + ReLU -> g_h ----------------------
__global__ void __launch_bounds__(256) k_gather1(const float* __restrict__ b1, int N) {
    int n = (blockIdx.x * 256 + threadIdx.x) >> 5;
    int l = threadIdx.x & 31;
    if (n >= N) return;

    float dn = g_dis[n];
    int cnt = g_zeroed[n];
    const int* cs = g_csr + g_rowstart[n] + g_bsum[n >> 10];

    // self-loop: dis[n] * xw[n]
    float2 v = __half22float2(g_xw[(size_t)n * 32 + l]);
    float2 acc = make_float2(dn * v.x, dn * v.y);

    int i = 0;
    for (; i + 4 <= cnt; i += 4) {
        int s0 = cs[i], s1 = cs[i+1], s2 = cs[i+2], s3 = cs[i+3];
        float d0 = g_dis[s0], d1 = g_dis[s1], d2 = g_dis[s2], d3 = g_dis[s3];
        float2 v0 = __half22float2(g_xw[(size_t)s0 * 32 + l]);
        float2 v1 = __half22float2(g_xw[(size_t)s1 * 32 + l]);
        float2 v2 = __half22float2(g_xw[(size_t)s2 * 32 + l]);
        float2 v3 = __half22float2(g_xw[(size_t)s3 * 32 + l]);
        acc.x = fmaf(d0, v0.x, acc.x); acc.y = fmaf(d0, v0.y, acc.y);
        acc.x = fmaf(d1, v1.x, acc.x); acc.y = fmaf(d1, v1.y, acc.y);
        acc.x = fmaf(d2, v2.x, acc.x); acc.y = fmaf(d2, v2.y, acc.y);
        acc.x = fmaf(d3, v3.x, acc.x); acc.y = fmaf(d3, v3.y, acc.y);
    }
    for (; i < cnt; i++) {
        int s = cs[i];
        float ds = g_dis[s];
        float2 vv = __half22float2(g_xw[(size_t)s * 32 + l]);
        acc.x = fmaf(ds, vv.x, acc.x); acc.y = fmaf(ds, vv.y, acc.y);
    }

    g_h[(size_t)n * NHID + l]      = fmaxf(fmaf(acc.x, dn, b1[l]),      0.0f);
    g_h[(size_t)n * NHID + 32 + l] = fmaxf(fmaf(acc.y, dn, b1[32 + l]), 0.0f);
}

// ---------------- layer-2 GEMM: 4 nodes/warp (crossbar-amortized) ----------------
__global__ void __launch_bounds__(256) k_gemm2(const float* __restrict__ W2, int N) {
    __shared__ float  W2p[NHID][64];   // W2p[k][2l]=W2[k][l], [2l+1]= (l<8 ? W2[k][32+l] : 0)
    __shared__ float4 xs[8][NHID];     // xs[w][k] = h[k] for 4 nodes

    int tid = threadIdx.x, w = tid >> 5, l = tid & 31;
    for (int idx = tid; idx < NHID * 64; idx += 256) ((float*)W2p)[idx] = 0.0f;
    __syncthreads();
    for (int idx = tid; idx < NHID * NCLASS; idx += 256) {
        int k = idx / NCLASS, c = idx % NCLASS;
        W2p[k][(c < 32) ? (2 * c) : (2 * (c - 32) + 1)] = W2[idx];
    }

    int n0 = (blockIdx.x * 8 + w) * 4;
    float* xsf = (float*)&xs[w][0];
    if (n0 < N) {
#pragma unroll
        for (int i = 0; i < 8; i++) {
            int el = l + 32 * i;            // 0..255
            int m = el >> 6, k = el & 63;
            int n = n0 + m;
            xsf[k * 4 + m] = (n < N) ? g_h[(size_t)n * NHID + k] : 0.0f;
        }
    }
    __syncthreads();
    if (n0 >= N) return;

    float y00 = 0.f, y01 = 0.f, y10 = 0.f, y11 = 0.f;
    float y20 = 0.f, y21 = 0.f, y30 = 0.f, y31 = 0.f;
#pragma unroll 4
    for (int k = 0; k < NHID; k++) {
        float4 xv = xs[w][k];
        float2 wv = *(const float2*)&W2p[k][l << 1];
        y00 = fmaf(xv.x, wv.x, y00);  y01 = fmaf(xv.x, wv.y, y01);
        y10 = fmaf(xv.y, wv.x, y10);  y11 = fmaf(xv.y, wv.y, y11);
        y20 = fmaf(xv.z, wv.x, y20);  y21 = fmaf(xv.z, wv.y, y21);
        y30 = fmaf(xv.w, wv.x, y30);  y31 = fmaf(xv.w, wv.y, y31);
    }
#pragma unroll
    for (int m = 0; m < 4; m++) {
        int n = n0 + m;
        if (n >= N) break;
        float dn = g_dis[n];
        float ya = (m == 0) ? y00 : (m == 1) ? y10 : (m == 2) ? y20 : y30;
        float yb = (m == 0) ? y01 : (m == 1) ? y11 : (m == 2) ? y21 : y31;
        g_hw[(size_t)n * 64 + l] = __float2half(ya * dn);
        if (l < 8) g_hw[(size_t)n * 64 + 32 + l] = __float2half(yb * dn);
    }
}

// ---------------- layer-2 aggregation + bias -> output --------------------------
__global__ void __launch_bounds__(256) k_gather2(const float* __restrict__ b2,
                                                 float* __restrict__ out, int N) {
    int n = (blockIdx.x * 256 + threadIdx.x) >> 5;
    int l = threadIdx.x & 31;
    if (n >= N) return;

    float a0 = __half2float(g_hw[(size_t)n * 64 + l]);                     // self-loop
    float a1 = (l < 8) ? __half2float(g_hw[(size_t)n * 64 + 32 + l]) : 0.0f;
    int cnt = g_zeroed[n];
    const int* cs = g_csr + g_rowstart[n] + g_bsum[n >> 10];

    int i = 0;
    for (; i + 4 <= cnt; i += 4) {
        int s0 = cs[i], s1 = cs[i+1], s2 = cs[i+2], s3 = cs[i+3];
        float b0 = __half2float(g_hw[(size_t)s0 * 64 + l]);
        float b1v = __half2float(g_hw[(size_t)s1 * 64 + l]);
        float b2v = __half2float(g_hw[(size_t)s2 * 64 + l]);
        float b3 = __half2float(g_hw[(size_t)s3 * 64 + l]);
        a0 += (b0 + b1v) + (b2v + b3);
        if (l < 8) {
            float c0 = __half2float(g_hw[(size_t)s0 * 64 + 32 + l]);
            float c1 = __half2float(g_hw[(size_t)s1 * 64 + 32 + l]);
            float c2 = __half2float(g_hw[(size_t)s2 * 64 + 32 + l]);
            float c3 = __half2float(g_hw[(size_t)s3 * 64 + 32 + l]);
            a1 += (c0 + c1) + (c2 + c3);
        }
    }
    for (; i < cnt; i++) {
        int s = cs[i];
        a0 += __half2float(g_hw[(size_t)s * 64 + l]);
        if (l < 8) a1 += __half2float(g_hw[(size_t)s * 64 + 32 + l]);
    }
    float dn = g_dis[n];
    out[(size_t)n * NCLASS + l] = fmaf(a0, dn, b2[l]);
    if (l < 8) out[(size_t)n * NCLASS + 32 + l] = fmaf(a1, dn, b2[32 + l]);
}

// ---------------- streams/events for captured fork (static init: mem delta = 0) -
struct ForkCtx {
    cudaStream_t s1;
    cudaEvent_t evA, evB;
    ForkCtx() {
        cudaStreamCreateWithFlags(&s1, cudaStreamNonBlocking);
        cudaEventCreateWithFlags(&evA, cudaEventDisableTiming);
        cudaEventCreateWithFlags(&evB, cudaEventDisableTiming);
    }
};
static ForkCtx g_fork;

// ---------------- launch ----------------
extern "C" void kernel_launch(void* const* d_in, const int* in_sizes, int n_in,
                              void* d_out, int out_size) {
    const float* X  = (const float*)d_in[0];
    const void*  ei = (const void*)d_in[1];
    const float* W1 = (const float*)d_in[2];
    const float* b1 = (const float*)d_in[3];
    const float* W2 = (const float*)d_in[4];
    const float* b2 = (const float*)d_in[5];
    float*       out = (float*)d_out;

    int N = in_sizes[0] / NFEAT;   // 100000
    int E = in_sizes[1] / 2;       // 1600000
    int nb = (N + 1023) / 1024;
    int eb2 = (E / 2 + 255) / 256;

    cudaStream_t s0 = cudaStreamPerThread;
    cudaStream_t s1 = g_fork.s1;

    // fork: gemm1 runs concurrently with the CSR chain
    cudaEventRecord(g_fork.evA, s0);
    cudaStreamWaitEvent(s1, g_fork.evA, 0);
    k_gemm1<<<(N + 31) / 32, 256, 0, s1>>>(X, W1, N);
    cudaEventRecord(g_fork.evB, s1);

    // CSR chain on s0
    void* z_addr = nullptr;
    cudaGetSymbolAddress(&z_addr, g_zeroed);
    cudaMemsetAsync(z_addr, 0, (size_t)(2 * NNODES + 1) * sizeof(int), s0);
    k_hist <<<eb2, 256, 0, s0>>>(ei, E, N);
    k_scan1<<<nb, 1024, 0, s0>>>(N);
    k_fill <<<eb2, 256, 0, s0>>>(ei, E, N);

    // join, then aggregation / layer-2 pipeline
    cudaStreamWaitEvent(s0, g_fork.evB, 0);
    k_gather1<<<(N + 7) / 8, 256, 0, s0>>>(b1, N);
    k_gemm2  <<<(N + 31) / 32, 256, 0, s0>>>(W2, N);
    k_gather2<<<(N + 7) / 8, 256, 0, s0>>>(b2, out, N);
}

// round 9
// speedup vs baseline: 2.2885x; 1.0185x over previous
#include <cuda_runtime.h>
#include <cuda_fp16.h>
#include <stdint.h>

#define NNODES 100000
#define NEDGES 1600000
#define NFEAT  128
#define NHID   64
#define NCLASS 40

// ---------------- scratch (static device globals; no allocation) ----------------
// self-cleaning region: [0,N)=cnt, [N,2N)=cursor, [2N]=scan ticket.
// Zero at load; every pipeline run re-zeroes it in k_gather2's epilogue.
__device__ int     g_zeroed[2 * NNODES + 1];
__device__ int     g_rowstart[NNODES];
__device__ int     g_bsum[128];
__device__ int     g_csr[NEDGES];
__device__ float   g_dis[NNODES];
// fp16 permuted: g_xw[n*32+l] = half2(col l, col l+32) of x@W1 (unscaled)
__device__ __half2 g_xw[(size_t)NNODES * 32];
__device__ __half  g_hw[(size_t)NNODES * 64];    // dis[n]*(h@W2), cols 0..39, 128B rows

// ---------------- threefry2x32, key = (0, 42) ----------------
__device__ __forceinline__ void threefry_0_42(uint32_t x0, uint32_t x1,
                                              uint32_t& o0, uint32_t& o1) {
    const uint32_t k0 = 0u, k1 = 42u;
    const uint32_t k2 = k0 ^ k1 ^ 0x1BD11BDAu;
    x0 += k0; x1 += k1;
#define TF_RND(R) { x0 += x1; x1 = (x1 << (R)) | (x1 >> (32 - (R))); x1 ^= x0; }
    TF_RND(13) TF_RND(15) TF_RND(26) TF_RND(6)   x0 += k1; x1 += k2 + 1u;
    TF_RND(17) TF_RND(29) TF_RND(16) TF_RND(24)  x0 += k2; x1 += k0 + 2u;
    TF_RND(13) TF_RND(15) TF_RND(26) TF_RND(6)   x0 += k0; x1 += k1 + 3u;
    TF_RND(17) TF_RND(29) TF_RND(16) TF_RND(24)  x0 += k1; x1 += k2 + 4u;
    TF_RND(13) TF_RND(15) TF_RND(26) TF_RND(6)   x0 += k2; x1 += k0 + 5u;
#undef TF_RND
    o0 = x0; o1 = x1;
}

// JAX threefry_partitionable bits32: bits = out0 ^ out1; keep = MSB==0
__device__ __forceinline__ bool dropout_keep(uint32_t e) {
    uint32_t o0, o1;
    threefry_0_42(0u, e, o0, o1);
    return ((o0 ^ o1) & 0x80000000u) == 0u;
}

// ---------------- dtype sniff (int64 values < 2^32 -> all hi-words zero) --------
__device__ __forceinline__ int sniff_is64(const void* ei) {
    const unsigned long long* p = (const unsigned long long*)ei;
    unsigned long long acc = 0;
#pragma unroll
    for (int i = 0; i < 64; i++) acc |= (p[i] >> 32);
    return acc == 0ull;
}

// ---------------- histogram over dst half (4 edges / thread) ----------------
__global__ void __launch_bounds__(256) k_hist(const void* __restrict__ ei, int E, int N) {
    __shared__ int s_is64;
    if (threadIdx.x == 0) s_is64 = sniff_is64(ei);
    __syncthreads();
    int e0 = (blockIdx.x * 256 + threadIdx.x) * 4;
    if (e0 >= E) return;
    int d[4];
    if (s_is64) {
        const longlong2* pd = (const longlong2*)((const long long*)ei + E);
        longlong2 a = pd[e0 >> 1], b = pd[(e0 >> 1) + 1];
        d[0] = (int)a.x; d[1] = (int)a.y; d[2] = (int)b.x; d[3] = (int)b.y;
    } else {
        const int4* pd = (const int4*)((const int*)ei + E);
        int4 v = pd[e0 >> 2];
        d[0] = v.x; d[1] = v.y; d[2] = v.z; d[3] = v.w;
    }
#pragma unroll
    for (int j = 0; j < 4; j++)
        if (e0 + j < E && (unsigned)d[j] < (unsigned)N) atomicAdd(&g_zeroed[d[j]], 1);
}

// ---------------- scan (warp-shuffle) + dis + decoupled final block scan --------
__global__ void __launch_bounds__(1024) k_scan1(int N) {
    __shared__ int wsum[32];
    __shared__ int woff[32];
    __shared__ int s_total;
    __shared__ int s_last;
    __shared__ int sm2[128];

    int tid = threadIdx.x;
    int i = blockIdx.x * 1024 + tid;
    int lane = tid & 31, wid = tid >> 5;

    int v = (i < N) ? g_zeroed[i] : 0;           // cnt
    if (i < N) g_dis[i] = rsqrtf((float)v + 1.0f);

    int inc = v;
#pragma unroll
    for (int o = 1; o < 32; o <<= 1) {
        int t = __shfl_up_sync(0xffffffffu, inc, o);
        if (lane >= o) inc += t;
    }
    if (lane == 31) wsum[wid] = inc;
    __syncthreads();
    if (wid == 0) {
        int w = wsum[lane];
        int winc = w;
#pragma unroll
        for (int o = 1; o < 32; o <<= 1) {
            int t = __shfl_up_sync(0xffffffffu, winc, o);
            if (lane >= o) winc += t;
        }
        woff[lane] = winc - w;
        if (lane == 31) s_total = winc;
    }
    __syncthreads();
    if (i < N) g_rowstart[i] = inc - v + woff[wid];

    if (tid == 0) {
        g_bsum[blockIdx.x] = s_total;
        __threadfence();
        int t = atomicAdd(&g_zeroed[2 * NNODES], 1);
        s_last = (t == (int)gridDim.x - 1);
    }
    __syncthreads();
    if (s_last) {
        __threadfence();
        int nb = gridDim.x;
        int val = 0;
        if (tid < 128) {
            val = (tid < nb) ? ((volatile int*)g_bsum)[tid] : 0;
            sm2[tid] = val;
        }
        __syncthreads();
        for (int o = 1; o < 128; o <<= 1) {
            int t = 0;
            if (tid < 128 && tid >= o) t = sm2[tid - o];
            __syncthreads();
            if (tid < 128) sm2[tid] += t;
            __syncthreads();
        }
        if (tid < nb) g_bsum[tid] = sm2[tid] - val;
    }
}

// ---------------- fill CSR (2 edges / thread, prefetched bases, paired atomics) -
__global__ void __launch_bounds__(256) k_fill(const void* __restrict__ ei, int E, int N) {
    __shared__ int s_is64;
    if (threadIdx.x == 0) s_is64 = sniff_is64(ei);
    __syncthreads();
    int e0 = (blockIdx.x * 256 + threadIdx.x) * 2;
    if (e0 >= E) return;
    int s0, d0, s1, d1;
    if (s_is64) {
        const longlong2* ps = (const longlong2*)ei;
        const longlong2* pd = (const longlong2*)((const long long*)ei + E);
        longlong2 sv = ps[e0 >> 1], dv = pd[e0 >> 1];
        s0 = (int)sv.x; s1 = (int)sv.y; d0 = (int)dv.x; d1 = (int)dv.y;
    } else {
        const int2* ps = (const int2*)ei;
        const int2* pd = (const int2*)((const int*)ei + E);
        int2 sv = ps[e0 >> 1], dv = pd[e0 >> 1];
        s0 = sv.x; s1 = sv.y; d0 = dv.x; d1 = dv.y;
    }
    bool ok0 = (unsigned)d0 < (unsigned)N && (unsigned)s0 < (unsigned)N;
    bool ok1 = (e0 + 1 < E) && (unsigned)d1 < (unsigned)N && (unsigned)s1 < (unsigned)N;
    int base0 = 0, base1 = 0, p0 = 0, p1 = 0;
    if (ok0) base0 = g_rowstart[d0] + g_bsum[d0 >> 10];   // prefetch before atomics
    if (ok1) base1 = g_rowstart[d1] + g_bsum[d1 >> 10];
    if (ok0) p0 = atomicAdd(&g_zeroed[NNODES + d0], 1);
    if (ok1) p1 = atomicAdd(&g_zeroed[NNODES + d1], 1);
    if (ok0) g_csr[base0 + p0] = s0;
    if (ok1) g_csr[base1 + p1] = s1;
}

// ---------------- layer-1 GEMM: 4 nodes/warp, fused dropout, fp16 out -----------
__global__ void __launch_bounds__(256) k_gemm1(const float* __restrict__ X,
                                               const float* __restrict__ W1, int N) {
    __shared__ float  Wp[NFEAT][NHID];   // Wp[k][2l] = W1[k][l], Wp[k][2l+1] = W1[k][l+32]
    __shared__ float4 xs[8][NFEAT];

    int tid = threadIdx.x, w = tid >> 5, l = tid & 31;
    for (int idx = tid; idx < NFEAT * NHID; idx += 256) {
        int k = idx >> 6, j = idx & 63;
        Wp[k][((j & 31) << 1) | (j >> 5)] = W1[idx];
    }

    int n0 = (blockIdx.x * 8 + w) * 4;
    float* xsf = (float*)&xs[w][0];
    if (n0 < N) {
#pragma unroll
        for (int i = 0; i < 16; i++) {
            int el = l + 32 * i;
            int m = el >> 7, f = el & 127;
            int n = n0 + m;
            float xv = 0.0f;
            if (n < N) {
                uint32_t e = (uint32_t)n * 128u + (uint32_t)f;
                float raw = X[(size_t)n * NFEAT + f] * 2.0f;
                xv = dropout_keep(e) ? raw : 0.0f;
            }
            xsf[f * 4 + m] = xv;
        }
    }
    __syncthreads();
    if (n0 >= N) return;

    float y00 = 0.f, y01 = 0.f, y10 = 0.f, y11 = 0.f;
    float y20 = 0.f, y21 = 0.f, y30 = 0.f, y31 = 0.f;
#pragma unroll 4
    for (int k = 0; k < NFEAT; k++) {
        float4 xv = xs[w][k];
        float2 wv = *(const float2*)&Wp[k][l << 1];
        y00 = fmaf(xv.x, wv.x, y00);  y01 = fmaf(xv.x, wv.y, y01);
        y10 = fmaf(xv.y, wv.x, y10);  y11 = fmaf(xv.y, wv.y, y11);
        y20 = fmaf(xv.z, wv.x, y20);  y21 = fmaf(xv.z, wv.y, y21);
        y30 = fmaf(xv.w, wv.x, y30);  y31 = fmaf(xv.w, wv.y, y31);
    }
    if (n0 + 0 < N) g_xw[(size_t)(n0    ) * 32 + l] = __floats2half2_rn(y00, y01);
    if (n0 + 1 < N) g_xw[(size_t)(n0 + 1) * 32 + l] = __floats2half2_rn(y10, y11);
    if (n0 + 2 < N) g_xw[(size_t)(n0 + 2) * 32 + l] = __floats2half2_rn(y20, y21);
    if (n0 + 3 < N) g_xw[(size_t)(n0 + 3) * 32 + l] = __floats2half2_rn(y30, y31);
}

// ---- layer-1 aggregation + bias + ReLU + layer-2 GEMM, fused (warp owns 4 nodes)
__global__ void __launch_bounds__(256) k_g1g2(const float* __restrict__ b1,
                                              const float* __restrict__ W2, int N) {
    __shared__ float  W2p[NHID][64];   // W2p[k][2c]=W2[k][c], [2c+1]=(c<8 ? W2[k][32+c] : 0)
    __shared__ float4 xs[8][NHID];     // per-warp h staging: xs[w][k] = h[k] for 4 nodes

    int tid = threadIdx.x, w = tid >> 5, l = tid & 31;
    for (int idx = tid; idx < NHID * 64; idx += 256) ((float*)W2p)[idx] = 0.0f;
    __syncthreads();
    for (int idx = tid; idx < NHID * NCLASS; idx += 256) {
        int k = idx / NCLASS, c = idx % NCLASS;
        W2p[k][(c < 32) ? (2 * c) : (2 * (c - 32) + 1)] = W2[idx];
    }
    __syncthreads();

    int n0 = blockIdx.x * 32 + w * 4;
    float* xsf = (float*)&xs[w][0];
    float bl0 = b1[l], bl1 = b1[32 + l];

#pragma unroll
    for (int m = 0; m < 4; m++) {
        int n = n0 + m;
        float h0 = 0.0f, h1 = 0.0f;
        if (n < N) {
            float dn = g_dis[n];
            int cnt = g_zeroed[n];
            const int* cs = g_csr + g_rowstart[n] + g_bsum[n >> 10];

            float2 v = __half22float2(g_xw[(size_t)n * 32 + l]);   // self-loop
            float2 acc = make_float2(dn * v.x, dn * v.y);

            int i = 0;
            for (; i + 4 <= cnt; i += 4) {
                int s0 = cs[i], s1 = cs[i+1], s2 = cs[i+2], s3 = cs[i+3];
                float d0 = g_dis[s0], d1 = g_dis[s1], d2 = g_dis[s2], d3 = g_dis[s3];
                float2 v0 = __half22float2(g_xw[(size_t)s0 * 32 + l]);
                float2 v1 = __half22float2(g_xw[(size_t)s1 * 32 + l]);
                float2 v2 = __half22float2(g_xw[(size_t)s2 * 32 + l]);
                float2 v3 = __half22float2(g_xw[(size_t)s3 * 32 + l]);
                acc.x = fmaf(d0, v0.x, acc.x); acc.y = fmaf(d0, v0.y, acc.y);
                acc.x = fmaf(d1, v1.x, acc.x); acc.y = fmaf(d1, v1.y, acc.y);
                acc.x = fmaf(d2, v2.x, acc.x); acc.y = fmaf(d2, v2.y, acc.y);
                acc.x = fmaf(d3, v3.x, acc.x); acc.y = fmaf(d3, v3.y, acc.y);
            }
            for (; i < cnt; i++) {
                int s = cs[i];
                float ds = g_dis[s];
                float2 vv = __half22float2(g_xw[(size_t)s * 32 + l]);
                acc.x = fmaf(ds, vv.x, acc.x); acc.y = fmaf(ds, vv.y, acc.y);
            }
            h0 = fmaxf(fmaf(acc.x, dn, bl0), 0.0f);
            h1 = fmaxf(fmaf(acc.y, dn, bl1), 0.0f);
        }
        xsf[l * 4 + m]        = h0;   // h[k=l]       for node m
        xsf[(l + 32) * 4 + m] = h1;   // h[k=l+32]    for node m
    }
    __syncwarp();
    if (n0 >= N) return;

    float y00 = 0.f, y01 = 0.f, y10 = 0.f, y11 = 0.f;
    float y20 = 0.f, y21 = 0.f, y30 = 0.f, y31 = 0.f;
#pragma unroll 4
    for (int k = 0; k < NHID; k++) {
        float4 xv = xs[w][k];
        float2 wv = *(const float2*)&W2p[k][l << 1];
        y00 = fmaf(xv.x, wv.x, y00);  y01 = fmaf(xv.x, wv.y, y01);
        y10 = fmaf(xv.y, wv.x, y10);  y11 = fmaf(xv.y, wv.y, y11);
        y20 = fmaf(xv.z, wv.x, y20);  y21 = fmaf(xv.z, wv.y, y21);
        y30 = fmaf(xv.w, wv.x, y30);  y31 = fmaf(xv.w, wv.y, y31);
    }
#pragma unroll
    for (int m = 0; m < 4; m++) {
        int n = n0 + m;
        if (n >= N) break;
        float dn = g_dis[n];
        float ya = (m == 0) ? y00 : (m == 1) ? y10 : (m == 2) ? y20 : y30;
        float yb = (m == 0) ? y01 : (m == 1) ? y11 : (m == 2) ? y21 : y31;
        g_hw[(size_t)n * 64 + l] = __float2half(ya * dn);
        if (l < 8) g_hw[(size_t)n * 64 + 32 + l] = __float2half(yb * dn);
    }
}

// ---------------- layer-2 aggregation + bias -> output; re-zero counters --------
__global__ void __launch_bounds__(256) k_gather2(const float* __restrict__ b2,
                                                 float* __restrict__ out, int N) {
    int n = (blockIdx.x * 256 + threadIdx.x) >> 5;
    int l = threadIdx.x & 31;
    if (n >= N) return;

    int cnt = g_zeroed[n];
    const int* cs = g_csr + g_rowstart[n] + g_bsum[n >> 10];

    float a0 = __half2float(g_hw[(size_t)n * 64 + l]);                     // self-loop
    float a1 = (l < 8) ? __half2float(g_hw[(size_t)n * 64 + 32 + l]) : 0.0f;

    int i = 0;
    for (; i + 4 <= cnt; i += 4) {
        int s0 = cs[i], s1 = cs[i+1], s2 = cs[i+2], s3 = cs[i+3];
        float b0 = __half2float(g_hw[(size_t)s0 * 64 + l]);
        float b1v = __half2float(g_hw[(size_t)s1 * 64 + l]);
        float b2v = __half2float(g_hw[(size_t)s2 * 64 + l]);
        float b3 = __half2float(g_hw[(size_t)s3 * 64 + l]);
        a0 += (b0 + b1v) + (b2v + b3);
        if (l < 8) {
            float c0 = __half2float(g_hw[(size_t)s0 * 64 + 32 + l]);
            float c1 = __half2float(g_hw[(size_t)s1 * 64 + 32 + l]);
            float c2 = __half2float(g_hw[(size_t)s2 * 64 + 32 + l]);
            float c3 = __half2float(g_hw[(size_t)s3 * 64 + 32 + l]);
            a1 += (c0 + c1) + (c2 + c3);
        }
    }
    for (; i < cnt; i++) {
        int s = cs[i];
        a0 += __half2float(g_hw[(size_t)s * 64 + l]);
        if (l < 8) a1 += __half2float(g_hw[(size_t)s * 64 + 32 + l]);
    }
    float dn = g_dis[n];
    out[(size_t)n * NCLASS + l] = fmaf(a0, dn, b2[l]);
    if (l < 8) out[(size_t)n * NCLASS + 32 + l] = fmaf(a1, dn, b2[32 + l]);

    // self-cleaning: restore zeroed region for the next pipeline run
    if (l == 0) g_zeroed[n] = 0;                       // cnt
    else if (l == 1) g_zeroed[NNODES + n] = 0;         // cursor
    else if (l == 2 && n == 0) g_zeroed[2 * NNODES] = 0;  // scan ticket
}

// ---------------- streams/events for captured fork (static init: mem delta = 0) -
struct ForkCtx {
    cudaStream_t s1;
    cudaEvent_t evA, evB;
    ForkCtx() {
        cudaStreamCreateWithFlags(&s1, cudaStreamNonBlocking);
        cudaEventCreateWithFlags(&evA, cudaEventDisableTiming);
        cudaEventCreateWithFlags(&evB, cudaEventDisableTiming);
    }
};
static ForkCtx g_fork;

// ---------------- launch ----------------
extern "C" void kernel_launch(void* const* d_in, const int* in_sizes, int n_in,
                              void* d_out, int out_size) {
    const float* X  = (const float*)d_in[0];
    const void*  ei = (const void*)d_in[1];
    const float* W1 = (const float*)d_in[2];
    const float* b1 = (const float*)d_in[3];
    const float* W2 = (const float*)d_in[4];
    const float* b2 = (const float*)d_in[5];
    float*       out = (float*)d_out;

    int N = in_sizes[0] / NFEAT;   // 100000
    int E = in_sizes[1] / 2;       // 1600000
    int nb = (N + 1023) / 1024;
    int eb2 = (E / 2 + 255) / 256;
    int eb4 = (E / 4 + 255) / 256;

    cudaStream_t s0 = cudaStreamPerThread;
    cudaStream_t s1 = g_fork.s1;

    // fork: gemm1 runs concurrently with the CSR chain
    cudaEventRecord(g_fork.evA, s0);
    cudaStreamWaitEvent(s1, g_fork.evA, 0);
    k_gemm1<<<(N + 31) / 32, 256, 0, s1>>>(X, W1, N);
    cudaEventRecord(g_fork.evB, s1);

    // CSR chain on s0 (counters pre-zeroed by previous run / static init)
    k_hist <<<eb4, 256, 0, s0>>>(ei, E, N);
    k_scan1<<<nb, 1024, 0, s0>>>(N);
    k_fill <<<eb2, 256, 0, s0>>>(ei, E, N);

    // join, then fused aggregation+layer-2, final aggregation
    cudaStreamWaitEvent(s0, g_fork.evB, 0);
    k_g1g2   <<<(N + 31) / 32, 256, 0, s0>>>(b1, W2, N);
    k_gather2<<<(N + 7) / 8, 256, 0, s0>>>(b2, out, N);
}

// round 10
// speedup vs baseline: 2.3204x; 1.0139x over previous
#include <cuda_runtime.h>
#include <cuda_fp16.h>
#include <stdint.h>

#define NNODES 100000
#define NEDGES 1600000
#define NFEAT  128
#define NHID   64
#define NCLASS 40

// ---------------- scratch (static device globals; no allocation) ----------------
// self-cleaning region: [0,N)=cnt, [N,2N)=cursor, [2N]=scan ticket.
__device__ int     g_zeroed[2 * NNODES + 1];
__device__ int     g_rowstart[NNODES];
__device__ int     g_bsum[128];
__device__ int     g_csr[NEDGES];
__device__ float   g_dis[NNODES];
// fp16 permuted: g_xw[n*32+l] = half2(col l, col l+32); after k_scale: pre-scaled by dis[n]
__device__ __half2 g_xw[(size_t)NNODES * 32];
// fp16 packed: g_hw2[n*20+c] = half2(col 2c, col 2c+1) of dis[n]*(h@W2), 80B rows
__device__ __half2 g_hw2[(size_t)NNODES * 20];

// ---------------- threefry2x32, key = (0, 42) ----------------
__device__ __forceinline__ void threefry_0_42(uint32_t x0, uint32_t x1,
                                              uint32_t& o0, uint32_t& o1) {
    const uint32_t k0 = 0u, k1 = 42u;
    const uint32_t k2 = k0 ^ k1 ^ 0x1BD11BDAu;
    x0 += k0; x1 += k1;
#define TF_RND(R) { x0 += x1; x1 = (x1 << (R)) | (x1 >> (32 - (R))); x1 ^= x0; }
    TF_RND(13) TF_RND(15) TF_RND(26) TF_RND(6)   x0 += k1; x1 += k2 + 1u;
    TF_RND(17) TF_RND(29) TF_RND(16) TF_RND(24)  x0 += k2; x1 += k0 + 2u;
    TF_RND(13) TF_RND(15) TF_RND(26) TF_RND(6)   x0 += k0; x1 += k1 + 3u;
    TF_RND(17) TF_RND(29) TF_RND(16) TF_RND(24)  x0 += k1; x1 += k2 + 4u;
    TF_RND(13) TF_RND(15) TF_RND(26) TF_RND(6)   x0 += k2; x1 += k0 + 5u;
#undef TF_RND
    o0 = x0; o1 = x1;
}

// JAX threefry_partitionable bits32: bits = out0 ^ out1; keep = MSB==0
__device__ __forceinline__ bool dropout_keep(uint32_t e) {
    uint32_t o0, o1;
    threefry_0_42(0u, e, o0, o1);
    return ((o0 ^ o1) & 0x80000000u) == 0u;
}

// ---------------- dtype sniff (int64 values < 2^32 -> all hi-words zero) --------
__device__ __forceinline__ int sniff_is64(const void* ei) {
    const unsigned long long* p = (const unsigned long long*)ei;
    unsigned long long acc = 0;
#pragma unroll
    for (int i = 0; i < 64; i++) acc |= (p[i] >> 32);
    return acc == 0ull;
}

// ---------------- histogram over dst half (4 edges / thread) ----------------
__global__ void __launch_bounds__(256) k_hist(const void* __restrict__ ei, int E, int N) {
    __shared__ int s_is64;
    if (threadIdx.x == 0) s_is64 = sniff_is64(ei);
    __syncthreads();
    int e0 = (blockIdx.x * 256 + threadIdx.x) * 4;
    if (e0 >= E) return;
    int d[4];
    if (s_is64) {
        const longlong2* pd = (const longlong2*)((const long long*)ei + E);
        longlong2 a = pd[e0 >> 1], b = pd[(e0 >> 1) + 1];
        d[0] = (int)a.x; d[1] = (int)a.y; d[2] = (int)b.x; d[3] = (int)b.y;
    } else {
        const int4* pd = (const int4*)((const int*)ei + E);
        int4 v = pd[e0 >> 2];
        d[0] = v.x; d[1] = v.y; d[2] = v.z; d[3] = v.w;
    }
#pragma unroll
    for (int j = 0; j < 4; j++)
        if (e0 + j < E && (unsigned)d[j] < (unsigned)N) atomicAdd(&g_zeroed[d[j]], 1);
}

// ---------------- scan (warp-shuffle) + dis + decoupled final block scan --------
__global__ void __launch_bounds__(1024) k_scan1(int N) {
    __shared__ int wsum[32];
    __shared__ int woff[32];
    __shared__ int s_total;
    __shared__ int s_last;
    __shared__ int sm2[128];

    int tid = threadIdx.x;
    int i = blockIdx.x * 1024 + tid;
    int lane = tid & 31, wid = tid >> 5;

    int v = (i < N) ? g_zeroed[i] : 0;
    if (i < N) g_dis[i] = rsqrtf((float)v + 1.0f);

    int inc = v;
#pragma unroll
    for (int o = 1; o < 32; o <<= 1) {
        int t = __shfl_up_sync(0xffffffffu, inc, o);
        if (lane >= o) inc += t;
    }
    if (lane == 31) wsum[wid] = inc;
    __syncthreads();
    if (wid == 0) {
        int w = wsum[lane];
        int winc = w;
#pragma unroll
        for (int o = 1; o < 32; o <<= 1) {
            int t = __shfl_up_sync(0xffffffffu, winc, o);
            if (lane >= o) winc += t;
        }
        woff[lane] = winc - w;
        if (lane == 31) s_total = winc;
    }
    __syncthreads();
    if (i < N) g_rowstart[i] = inc - v + woff[wid];

    if (tid == 0) {
        g_bsum[blockIdx.x] = s_total;
        __threadfence();
        int t = atomicAdd(&g_zeroed[2 * NNODES], 1);
        s_last = (t == (int)gridDim.x - 1);
    }
    __syncthreads();
    if (s_last) {
        __threadfence();
        int nb = gridDim.x;
        int val = 0;
        if (tid < 128) {
            val = (tid < nb) ? ((volatile int*)g_bsum)[tid] : 0;
            sm2[tid] = val;
        }
        __syncthreads();
        for (int o = 1; o < 128; o <<= 1) {
            int t = 0;
            if (tid < 128 && tid >= o) t = sm2[tid - o];
            __syncthreads();
            if (tid < 128) sm2[tid] += t;
            __syncthreads();
        }
        if (tid < nb) g_bsum[tid] = sm2[tid] - val;
    }
}

// ---------------- fill CSR (4 edges / thread, batched atomics) ------------------
__global__ void __launch_bounds__(256) k_fill(const void* __restrict__ ei, int E, int N) {
    __shared__ int s_is64;
    if (threadIdx.x == 0) s_is64 = sniff_is64(ei);
    __syncthreads();
    int e0 = (blockIdx.x * 256 + threadIdx.x) * 4;
    if (e0 >= E) return;
    int s[4], d[4];
    if (s_is64) {
        const longlong2* ps = (const longlong2*)ei;
        const longlong2* pd = (const longlong2*)((const long long*)ei + E);
        longlong2 sa = ps[e0 >> 1], sb = ps[(e0 >> 1) + 1];
        longlong2 da = pd[e0 >> 1], db = pd[(e0 >> 1) + 1];
        s[0] = (int)sa.x; s[1] = (int)sa.y; s[2] = (int)sb.x; s[3] = (int)sb.y;
        d[0] = (int)da.x; d[1] = (int)da.y; d[2] = (int)db.x; d[3] = (int)db.y;
    } else {
        const int4* ps = (const int4*)ei;
        const int4* pd = (const int4*)((const int*)ei + E);
        int4 sv = ps[e0 >> 2], dv = pd[e0 >> 2];
        s[0] = sv.x; s[1] = sv.y; s[2] = sv.z; s[3] = sv.w;
        d[0] = dv.x; d[1] = dv.y; d[2] = dv.z; d[3] = dv.w;
    }
    bool ok[4];
    int base[4], p[4];
#pragma unroll
    for (int j = 0; j < 4; j++)
        ok[j] = (e0 + j < E) && (unsigned)d[j] < (unsigned)N && (unsigned)s[j] < (unsigned)N;
#pragma unroll
    for (int j = 0; j < 4; j++)
        if (ok[j]) base[j] = g_rowstart[d[j]] + g_bsum[d[j] >> 10];
#pragma unroll
    for (int j = 0; j < 4; j++)
        if (ok[j]) p[j] = atomicAdd(&g_zeroed[NNODES + d[j]], 1);
#pragma unroll
    for (int j = 0; j < 4; j++)
        if (ok[j]) g_csr[base[j] + p[j]] = s[j];
}

// ---------------- layer-1 GEMM: 4 nodes/warp, fused dropout, fp16 out -----------
__global__ void __launch_bounds__(256) k_gemm1(const float* __restrict__ X,
                                               const float* __restrict__ W1, int N) {
    __shared__ float  Wp[NFEAT][NHID];   // Wp[k][2l] = W1[k][l], Wp[k][2l+1] = W1[k][l+32]
    __shared__ float4 xs[8][NFEAT];

    int tid = threadIdx.x, w = tid >> 5, l = tid & 31;
    for (int idx = tid; idx < NFEAT * NHID; idx += 256) {
        int k = idx >> 6, j = idx & 63;
        Wp[k][((j & 31) << 1) | (j >> 5)] = W1[idx];
    }

    int n0 = (blockIdx.x * 8 + w) * 4;
    float* xsf = (float*)&xs[w][0];
    if (n0 < N) {
#pragma unroll
        for (int i = 0; i < 16; i++) {
            int el = l + 32 * i;
            int m = el >> 7, f = el & 127;
            int n = n0 + m;
            float xv = 0.0f;
            if (n < N) {
                uint32_t e = (uint32_t)n * 128u + (uint32_t)f;
                float raw = X[(size_t)n * NFEAT + f] * 2.0f;
                xv = dropout_keep(e) ? raw : 0.0f;
            }
            xsf[f * 4 + m] = xv;
        }
    }
    __syncthreads();
    if (n0 >= N) return;

    float y00 = 0.f, y01 = 0.f, y10 = 0.f, y11 = 0.f;
    float y20 = 0.f, y21 = 0.f, y30 = 0.f, y31 = 0.f;
#pragma unroll 4
    for (int k = 0; k < NFEAT; k++) {
        float4 xv = xs[w][k];
        float2 wv = *(const float2*)&Wp[k][l << 1];
        y00 = fmaf(xv.x, wv.x, y00);  y01 = fmaf(xv.x, wv.y, y01);
        y10 = fmaf(xv.y, wv.x, y10);  y11 = fmaf(xv.y, wv.y, y11);
        y20 = fmaf(xv.z, wv.x, y20);  y21 = fmaf(xv.z, wv.y, y21);
        y30 = fmaf(xv.w, wv.x, y30);  y31 = fmaf(xv.w, wv.y, y31);
    }
    if (n0 + 0 < N) g_xw[(size_t)(n0    ) * 32 + l] = __floats2half2_rn(y00, y01);
    if (n0 + 1 < N) g_xw[(size_t)(n0 + 1) * 32 + l] = __floats2half2_rn(y10, y11);
    if (n0 + 2 < N) g_xw[(size_t)(n0 + 2) * 32 + l] = __floats2half2_rn(y20, y21);
    if (n0 + 3 < N) g_xw[(size_t)(n0 + 3) * 32 + l] = __floats2half2_rn(y30, y31);
}

// ---------------- pre-scale g_xw rows by dis[n] (in place) ----------------------
__global__ void __launch_bounds__(256) k_scale(int N) {
    int i = blockIdx.x * 256 + threadIdx.x;
    if (i >= N * 32) return;
    float d = g_dis[i >> 5];                       // warp-uniform broadcast
    float2 v = __half22float2(g_xw[i]);
    g_xw[i] = __floats2half2_rn(v.x * d, v.y * d);
}

// ---- layer-1 aggregation + bias + ReLU + layer-2 GEMM (warp owns 4 nodes) ------
// g_xw is pre-scaled: agg = xws[n] + sum_s xws[s];  h = relu(dn*agg + b1)
__global__ void __launch_bounds__(256) k_g1g2(const float* __restrict__ b1,
                                              const float* __restrict__ W2, int N) {
    __shared__ float  W2p[NHID][64];   // W2p[k][2c]=W2[k][c], [2c+1]=(c<8 ? W2[k][32+c] : 0)
    __shared__ float4 xs[8][NHID];

    int tid = threadIdx.x, w = tid >> 5, l = tid & 31;
    for (int idx = tid; idx < NHID * 64; idx += 256) ((float*)W2p)[idx] = 0.0f;
    __syncthreads();
    for (int idx = tid; idx < NHID * NCLASS; idx += 256) {
        int k = idx / NCLASS, c = idx % NCLASS;
        W2p[k][(c < 32) ? (2 * c) : (2 * (c - 32) + 1)] = W2[idx];
    }
    __syncthreads();

    int n0 = blockIdx.x * 32 + w * 4;
    float* xsf = (float*)&xs[w][0];
    float bl0 = b1[l], bl1 = b1[32 + l];
    float dns[4];

#pragma unroll
    for (int m = 0; m < 4; m++) {
        int n = n0 + m;
        float h0 = 0.0f, h1 = 0.0f, dn = 0.0f;
        if (n < N) {
            dn = g_dis[n];
            int cnt = g_zeroed[n];
            const int* cs = g_csr + g_rowstart[n] + g_bsum[n >> 10];

            float2 acc = __half22float2(g_xw[(size_t)n * 32 + l]);   // self (pre-scaled)

            for (int ch = 0; ch < cnt; ch += 32) {
                int m2 = min(32, cnt - ch);
                int sidx = (l < m2) ? cs[ch + l] : 0;    // one coalesced LDG / chunk
                int j = 0;
                for (; j + 4 <= m2; j += 4) {
                    int s0 = __shfl_sync(0xffffffffu, sidx, j);
                    int s1 = __shfl_sync(0xffffffffu, sidx, j + 1);
                    int s2 = __shfl_sync(0xffffffffu, sidx, j + 2);
                    int s3 = __shfl_sync(0xffffffffu, sidx, j + 3);
                    float2 v0 = __half22float2(g_xw[(size_t)s0 * 32 + l]);
                    float2 v1 = __half22float2(g_xw[(size_t)s1 * 32 + l]);
                    float2 v2 = __half22float2(g_xw[(size_t)s2 * 32 + l]);
                    float2 v3 = __half22float2(g_xw[(size_t)s3 * 32 + l]);
                    acc.x += (v0.x + v1.x) + (v2.x + v3.x);
                    acc.y += (v0.y + v1.y) + (v2.y + v3.y);
                }
                for (; j < m2; j++) {
                    int s = __shfl_sync(0xffffffffu, sidx, j);
                    float2 v = __half22float2(g_xw[(size_t)s * 32 + l]);
                    acc.x += v.x; acc.y += v.y;
                }
            }
            h0 = fmaxf(fmaf(acc.x, dn, bl0), 0.0f);
            h1 = fmaxf(fmaf(acc.y, dn, bl1), 0.0f);
        }
        dns[m] = dn;
        xsf[l * 4 + m]        = h0;
        xsf[(l + 32) * 4 + m] = h1;
    }
    __syncwarp();
    if (n0 >= N) return;

    float y00 = 0.f, y01 = 0.f, y10 = 0.f, y11 = 0.f;
    float y20 = 0.f, y21 = 0.f, y30 = 0.f, y31 = 0.f;
#pragma unroll 4
    for (int k = 0; k < NHID; k++) {
        float4 xv = xs[w][k];
        float2 wv = *(const float2*)&W2p[k][l << 1];
        y00 = fmaf(xv.x, wv.x, y00);  y01 = fmaf(xv.x, wv.y, y01);
        y10 = fmaf(xv.y, wv.x, y10);  y11 = fmaf(xv.y, wv.y, y11);
        y20 = fmaf(xv.z, wv.x, y20);  y21 = fmaf(xv.z, wv.y, y21);
        y30 = fmaf(xv.w, wv.x, y30);  y31 = fmaf(xv.w, wv.y, y31);
    }

    // pack into 80B half2 rows: g_hw2[n*20+l] = (col 2l, col 2l+1)
    int c2 = (l < 16) ? (2 * l) : (2 * (l - 16));
#pragma unroll
    for (int m = 0; m < 4; m++) {
        int n = n0 + m;
        if (n >= N) break;
        float ya = (m == 0) ? y00 : (m == 1) ? y10 : (m == 2) ? y20 : y30;
        float yb = (m == 0) ? y01 : (m == 1) ? y11 : (m == 2) ? y21 : y31;
        float pa0 = __shfl_sync(0xffffffffu, ya, c2);
        float pa1 = __shfl_sync(0xffffffffu, ya, c2 + 1);
        float pb0 = __shfl_sync(0xffffffffu, yb, c2);
        float pb1 = __shfl_sync(0xffffffffu, yb, c2 + 1);
        float pa = (l < 16) ? pa0 : pb0;
        float pb = (l < 16) ? pa1 : pb1;
        if (l < 20)
            g_hw2[(size_t)n * 20 + l] = __floats2half2_rn(pa * dns[m], pb * dns[m]);
    }
}

// ---------------- layer-2 aggregation + bias -> output; re-zero counters --------
__global__ void __launch_bounds__(256) k_gather2(const float* __restrict__ b2,
                                                 float* __restrict__ out, int N) {
    int n = (blockIdx.x * 256 + threadIdx.x) >> 5;
    int l = threadIdx.x & 31;
    if (n >= N) return;

    int cnt = g_zeroed[n];
    const int* cs = g_csr + g_rowstart[n] + g_bsum[n >> 10];

    float2 acc = make_float2(0.0f, 0.0f);
    if (l < 20) acc = __half22float2(g_hw2[(size_t)n * 20 + l]);   // self

    for (int ch = 0; ch < cnt; ch += 32) {
        int m2 = min(32, cnt - ch);
        int sidx = (l < m2) ? cs[ch + l] : 0;
        int j = 0;
        for (; j + 4 <= m2; j += 4) {
            int s0 = __shfl_sync(0xffffffffu, sidx, j);
            int s1 = __shfl_sync(0xffffffffu, sidx, j + 1);
            int s2 = __shfl_sync(0xffffffffu, sidx, j + 2);
            int s3 = __shfl_sync(0xffffffffu, sidx, j + 3);
            if (l < 20) {
                float2 v0 = __half22float2(g_hw2[(size_t)s0 * 20 + l]);
                float2 v1 = __half22float2(g_hw2[(size_t)s1 * 20 + l]);
                float2 v2 = __half22float2(g_hw2[(size_t)s2 * 20 + l]);
                float2 v3 = __half22float2(g_hw2[(size_t)s3 * 20 + l]);
                acc.x += (v0.x + v1.x) + (v2.x + v3.x);
                acc.y += (v0.y + v1.y) + (v2.y + v3.y);
            }
        }
        for (; j < m2; j++) {
            int s = __shfl_sync(0xffffffffu, sidx, j);
            if (l < 20) {
                float2 v = __half22float2(g_hw2[(size_t)s * 20 + l]);
                acc.x += v.x; acc.y += v.y;
            }
        }
    }
    float dn = g_dis[n];
    if (l < 20) {
        float2 bb = *(const float2*)&b2[2 * l];
        float2 o = make_float2(fmaf(acc.x, dn, bb.x), fmaf(acc.y, dn, bb.y));
        *(float2*)&out[(size_t)n * NCLASS + 2 * l] = o;
    }

    // self-cleaning: restore zeroed region for the next pipeline run
    if (l == 0) g_zeroed[n] = 0;                          // cnt
    else if (l == 1) g_zeroed[NNODES + n] = 0;            // cursor
    else if (l == 2 && n == 0) g_zeroed[2 * NNODES] = 0;  // scan ticket
}

// ---------------- streams/events for captured fork (static init: mem delta = 0) -
struct ForkCtx {
    cudaStream_t s1;
    cudaEvent_t evA, evB;
    ForkCtx() {
        cudaStreamCreateWithFlags(&s1, cudaStreamNonBlocking);
        cudaEventCreateWithFlags(&evA, cudaEventDisableTiming);
        cudaEventCreateWithFlags(&evB, cudaEventDisableTiming);
    }
};
static ForkCtx g_fork;

// ---------------- launch ----------------
extern "C" void kernel_launch(void* const* d_in, const int* in_sizes, int n_in,
                              void* d_out, int out_size) {
    const float* X  = (const float*)d_in[0];
    const void*  ei = (const void*)d_in[1];
    const float* W1 = (const float*)d_in[2];
    const float* b1 = (const float*)d_in[3];
    const float* W2 = (const float*)d_in[4];
    const float* b2 = (const float*)d_in[5];
    float*       out = (float*)d_out;

    int N = in_sizes[0] / NFEAT;   // 100000
    int E = in_sizes[1] / 2;       // 1600000
    int nb = (N + 1023) / 1024;
    int eb4 = (E / 4 + 255) / 256;

    cudaStream_t s0 = cudaStreamPerThread;
    cudaStream_t s1 = g_fork.s1;

    // fork: gemm1 runs concurrently with the CSR chain
    cudaEventRecord(g_fork.evA, s0);
    cudaStreamWaitEvent(s1, g_fork.evA, 0);
    k_gemm1<<<(N + 31) / 32, 256, 0, s1>>>(X, W1, N);
    cudaEventRecord(g_fork.evB, s1);

    // CSR chain on s0 (counters pre-zeroed by previous run / static init)
    k_hist <<<eb4, 256, 0, s0>>>(ei, E, N);
    k_scan1<<<nb, 1024, 0, s0>>>(N);
    k_fill <<<eb4, 256, 0, s0>>>(ei, E, N);

    // join, then prescale + fused aggregation/layer-2 + final aggregation
    cudaStreamWaitEvent(s0, g_fork.evB, 0);
    k_scale  <<<(N * 32 + 255) / 256, 256, 0, s0>>>(N);
    k_g1g2   <<<(N + 31) / 32, 256, 0, s0>>>(b1, W2, N);
    k_gather2<<<(N + 7) / 8, 256, 0, s0>>>(b2, out, N);
}